// round 3
// baseline (speedup 1.0000x reference)
#include <cuda_runtime.h>
#include <cuda_bf16.h>
#include <math.h>

// Problem constants (fixed by the reference): B=2, S=2048, H=1024, nh=16, hd=64
#define BATCH 2
#define SEQ   2048
#define HID   1024
#define NH    16
#define HD    64
#define ROWS  (BATCH * SEQ)        // 4096
#define QKV_COLS (3 * HID)         // 3072

// Scratch (no allocations allowed; use __device__ globals)
__device__ float g_qkv[ROWS * QKV_COLS];   // [4096, 3072]
__device__ float g_attn[ROWS * HID];       // [4096, 1024]

// ---------------------------------------------------------------------------
// SGEMM: C[M,N] = A[M,K] @ B[N,K]^T   (both K-contiguous row-major)
// 128x128 tile, TK=8, 256 threads, 8x8 microtile.
// ---------------------------------------------------------------------------
#define GTM 128
#define GTN 128
#define GTK 8
#define GPAD 132   // padded smem row stride (conflict-free writes, float4-aligned)

__global__ __launch_bounds__(256, 2)
void sgemm_abt(const float* __restrict__ A, const float* __restrict__ B,
               float* __restrict__ C, int M, int N, int K) {
    __shared__ float As[GTK][GPAD];
    __shared__ float Bs[GTK][GPAD];

    const int bm = blockIdx.y * GTM;
    const int bn = blockIdx.x * GTN;
    const int tid = threadIdx.x;
    const int tx = tid & 15;        // 0..15  -> N microtile
    const int ty = tid >> 4;        // 0..15  -> M microtile

    const int lr = tid >> 1;        // load row within tile (0..127)
    const int lq = (tid & 1) * 4;   // load col quad (0 or 4)

    const float* Ap = A + (size_t)(bm + lr) * K + lq;
    const float* Bp = B + (size_t)(bn + lr) * K + lq;

    float acc[8][8] = {};

    for (int k0 = 0; k0 < K; k0 += GTK) {
        float4 av = *(const float4*)(Ap + k0);
        float4 bv = *(const float4*)(Bp + k0);
        __syncthreads();
        As[lq + 0][lr] = av.x; As[lq + 1][lr] = av.y;
        As[lq + 2][lr] = av.z; As[lq + 3][lr] = av.w;
        Bs[lq + 0][lr] = bv.x; Bs[lq + 1][lr] = bv.y;
        Bs[lq + 2][lr] = bv.z; Bs[lq + 3][lr] = bv.w;
        __syncthreads();

#pragma unroll
        for (int k = 0; k < GTK; k++) {
            float ar[8], br[8];
            *(float4*)(ar)     = *(const float4*)&As[k][ty * 8];
            *(float4*)(ar + 4) = *(const float4*)&As[k][ty * 8 + 4];
            *(float4*)(br)     = *(const float4*)&Bs[k][tx * 8];
            *(float4*)(br + 4) = *(const float4*)&Bs[k][tx * 8 + 4];
#pragma unroll
            for (int i = 0; i < 8; i++)
#pragma unroll
                for (int j = 0; j < 8; j++)
                    acc[i][j] = fmaf(ar[i], br[j], acc[i][j]);
        }
    }

#pragma unroll
    for (int i = 0; i < 8; i++) {
        float* crow = C + (size_t)(bm + ty * 8 + i) * N + bn + tx * 8;
        *(float4*)(crow)     = make_float4(acc[i][0], acc[i][1], acc[i][2], acc[i][3]);
        *(float4*)(crow + 4) = make_float4(acc[i][4], acc[i][5], acc[i][6], acc[i][7]);
    }
}

// ---------------------------------------------------------------------------
// Flash attention: per (b, h) block of 64 queries; online softmax over S=2048.
// Block = 256 threads as 16x16 grid; each thread: 4 rows x 4 cols.
// smem: Qs[64][64], Ks[64][65], Vs[64][64], Ps[64][65]  -> 66048 bytes dynamic.
// ---------------------------------------------------------------------------
#define FBM 64
#define FBN 64
#define QS_ 64
#define KS_ 65
#define VS_ 64
#define PS_ 65
#define FLASH_SMEM ((FBM * QS_ + FBN * KS_ + FBN * VS_ + FBM * PS_) * 4)

__global__ __launch_bounds__(256)
void flash_kernel(const float* __restrict__ qkv, float* __restrict__ attn) {
    extern __shared__ float sm[];
    float* Qs = sm;                       // FBM*QS_
    float* Ks = Qs + FBM * QS_;           // FBN*KS_
    float* Vs = Ks + FBN * KS_;           // FBN*VS_
    float* Ps = Vs + FBN * VS_;           // FBM*PS_

    const int qb = blockIdx.x * FBM;
    const int h  = blockIdx.y;
    const int b  = blockIdx.z;
    const int tid = threadIdx.x;
    const int tx = tid & 15;
    const int ty = tid >> 4;
    const int i0 = ty * 4;   // query rows
    const int j0 = tx * 4;   // key cols (scores)
    const int d0 = tx * 4;   // head dims (output)

    const float scale = 0.125f;  // 1/sqrt(64)
    const size_t rs = QKV_COLS;  // 3072
    const float* qg = qkv + (size_t)(b * SEQ + qb) * rs + h * HD;        // Q
    const float* kg = qkv + (size_t)(b * SEQ) * rs + HID + h * HD;       // K
    const float* vg = qkv + (size_t)(b * SEQ) * rs + 2 * HID + h * HD;   // V

    // Load Q tile (64 rows x 64 cols = 1024 float4s, 4 per thread)
    for (int e = tid; e < FBM * 16; e += 256) {
        int r = e >> 4, c = (e & 15) * 4;
        float4 v = *(const float4*)(qg + (size_t)r * rs + c);
        float* q = Qs + r * QS_ + c;
        q[0] = v.x; q[1] = v.y; q[2] = v.z; q[3] = v.w;
    }

    float m[4], l[4], o[4][4];
#pragma unroll
    for (int i = 0; i < 4; i++) {
        m[i] = -1e30f; l[i] = 0.f;
#pragma unroll
        for (int d = 0; d < 4; d++) o[i][d] = 0.f;
    }
    __syncthreads();

    for (int kb = 0; kb < SEQ; kb += FBN) {
        // Load K, V tiles
        for (int e = tid; e < FBN * 16; e += 256) {
            int r = e >> 4, c = (e & 15) * 4;
            float4 kv = *(const float4*)(kg + (size_t)(kb + r) * rs + c);
            float* kp = Ks + r * KS_ + c;
            kp[0] = kv.x; kp[1] = kv.y; kp[2] = kv.z; kp[3] = kv.w;
            float4 vv = *(const float4*)(vg + (size_t)(kb + r) * rs + c);
            *(float4*)(Vs + r * VS_ + c) = vv;
        }
        __syncthreads();

        // S = Q @ K^T
        float s[4][4] = {};
#pragma unroll 8
        for (int d = 0; d < HD; d++) {
            float qr[4], kr[4];
#pragma unroll
            for (int i = 0; i < 4; i++) qr[i] = Qs[(i0 + i) * QS_ + d];
#pragma unroll
            for (int j = 0; j < 4; j++) kr[j] = Ks[(j0 + j) * KS_ + d];
#pragma unroll
            for (int i = 0; i < 4; i++)
#pragma unroll
                for (int j = 0; j < 4; j++)
                    s[i][j] = fmaf(qr[i], kr[j], s[i][j]);
        }

        // Online softmax update (row groups of 16 threads within half-warps)
#pragma unroll
        for (int i = 0; i < 4; i++) {
            float t0 = fmaxf(fmaxf(s[i][0], s[i][1]), fmaxf(s[i][2], s[i][3]));
            t0 *= scale;
#pragma unroll
            for (int off = 8; off >= 1; off >>= 1)
                t0 = fmaxf(t0, __shfl_xor_sync(0xffffffffu, t0, off));
            float mn = fmaxf(m[i], t0);
            float corr = __expf(m[i] - mn);
            m[i] = mn;
            float rsum = 0.f;
#pragma unroll
            for (int j = 0; j < 4; j++) {
                float p = __expf(fmaf(s[i][j], scale, -mn));
                s[i][j] = p;
                rsum += p;
            }
#pragma unroll
            for (int off = 8; off >= 1; off >>= 1)
                rsum += __shfl_xor_sync(0xffffffffu, rsum, off);
            l[i] = l[i] * corr + rsum;
#pragma unroll
            for (int d = 0; d < 4; d++) o[i][d] *= corr;
        }

        // Stage P tile to smem
#pragma unroll
        for (int i = 0; i < 4; i++)
#pragma unroll
            for (int j = 0; j < 4; j++)
                Ps[(i0 + i) * PS_ + j0 + j] = s[i][j];
        __syncthreads();

        // O += P @ V
#pragma unroll 8
        for (int j = 0; j < FBN; j++) {
            float vr[4], pr[4];
            *(float4*)vr = *(const float4*)(Vs + j * VS_ + d0);
#pragma unroll
            for (int i = 0; i < 4; i++) pr[i] = Ps[(i0 + i) * PS_ + j];
#pragma unroll
            for (int i = 0; i < 4; i++)
#pragma unroll
                for (int d = 0; d < 4; d++)
                    o[i][d] = fmaf(pr[i], vr[d], o[i][d]);
        }
        __syncthreads();
    }

    // Epilogue: normalize, write attn in [B, S, H] layout (head-contiguous)
#pragma unroll
    for (int i = 0; i < 4; i++) {
        float inv = 1.0f / l[i];
        float* out = attn + (size_t)(b * SEQ + qb + i0 + i) * HID + h * HD + d0;
        *(float4*)out = make_float4(o[i][0] * inv, o[i][1] * inv,
                                    o[i][2] * inv, o[i][3] * inv);
    }
}

// ---------------------------------------------------------------------------
extern "C" void kernel_launch(void* const* d_in, const int* in_sizes, int n_in,
                              void* d_out, int out_size) {
    const float* hidden = (const float*)d_in[0];   // [2, 2048, 1024]
    const float* w_qkv  = (const float*)d_in[1];   // [3072, 1024]
    const float* w_o    = (const float*)d_in[2];   // [1024, 1024]
    float* out = (float*)d_out;                    // [2, 2048, 1024]

    float* qkv_ptr = nullptr;
    float* attn_ptr = nullptr;
    cudaGetSymbolAddress((void**)&qkv_ptr, g_qkv);
    cudaGetSymbolAddress((void**)&attn_ptr, g_attn);

    static bool attr_set = false;
    if (!attr_set) {
        cudaFuncSetAttribute(flash_kernel,
                             cudaFuncAttributeMaxDynamicSharedMemorySize,
                             FLASH_SMEM);
        attr_set = true;
    }

    // 1) QKV projection: [4096,1024] @ [3072,1024]^T -> [4096,3072]
    {
        dim3 grid(QKV_COLS / GTN, ROWS / GTM);
        sgemm_abt<<<grid, 256>>>(hidden, w_qkv, qkv_ptr, ROWS, QKV_COLS, HID);
    }

    // 2) Flash attention -> g_attn in [B,S,H]
    {
        dim3 grid(SEQ / FBM, NH, BATCH);
        flash_kernel<<<grid, 256, FLASH_SMEM>>>(qkv_ptr, attn_ptr);
    }

    // 3) Output projection: [4096,1024] @ [1024,1024]^T -> [4096,1024]
    {
        dim3 grid(HID / GTN, ROWS / GTM);
        sgemm_abt<<<grid, 256>>>(attn_ptr, w_o, out, ROWS, HID, HID);
    }
}

// round 4
// speedup vs baseline: 2.7405x; 2.7405x over previous
#include <cuda_runtime.h>
#include <math.h>

// Problem constants: B=2, S=2048, H=1024, nh=16, hd=64
#define BATCH 2
#define SEQ   2048
#define HID   1024
#define NH    16
#define HD    64
#define ROWS  (BATCH * SEQ)        // 4096
#define QKV_COLS (3 * HID)         // 3072

__device__ float g_qkv[ROWS * QKV_COLS];
__device__ float g_attn[ROWS * HID];

// ---------------------------------------------------------------------------
// TF32 helpers
// ---------------------------------------------------------------------------
__device__ __forceinline__ unsigned f2tf(float x) {
    unsigned u;
    asm("cvt.rna.tf32.f32 %0, %1;" : "=r"(u) : "f"(x));
    return u;
}

__device__ __forceinline__ void mma_tf32(float c[4], const unsigned a[4],
                                         const unsigned b[2]) {
    asm volatile(
        "mma.sync.aligned.m16n8k8.row.col.f32.tf32.tf32.f32 "
        "{%0,%1,%2,%3}, {%4,%5,%6,%7}, {%8,%9}, {%0,%1,%2,%3};\n"
        : "+f"(c[0]), "+f"(c[1]), "+f"(c[2]), "+f"(c[3])
        : "r"(a[0]), "r"(a[1]), "r"(a[2]), "r"(a[3]), "r"(b[0]), "r"(b[1]));
}

// ---------------------------------------------------------------------------
// GEMM: C[M,N] = A[M,K] @ B[N,K]^T, tf32 tensor-core path.
// Block 128x128x32, 256 threads = 8 warps (2 m x 4 n), warp tile 64x32.
// smem stride 36 words: fragment LDS address = 36*g + t = 4g+t (mod 32), CF.
// ---------------------------------------------------------------------------
#define TBM 128
#define TBN 128
#define TBK 32
#define TST 36

__global__ __launch_bounds__(256, 1)
void gemm_tf32(const float* __restrict__ A, const float* __restrict__ B,
               float* __restrict__ C, int M, int N, int K) {
    __shared__ unsigned As[TBM * TST];
    __shared__ unsigned Bs[TBN * TST];

    const int bm = blockIdx.y * TBM, bn = blockIdx.x * TBN;
    const int tid = threadIdx.x;
    const int rl = tid >> 3;          // load row 0..31
    const int kq = (tid & 7) * 4;     // load k quad
    const float* Ap = A + (size_t)(bm + rl) * K + kq;
    const float* Bp = B + (size_t)(bn + rl) * K + kq;

    const int wid = tid >> 5, lane = tid & 31;
    const int wm = wid & 1, wn = wid >> 1;
    const int g = lane >> 2, t = lane & 3;

    float acc[4][4][4];
#pragma unroll
    for (int i = 0; i < 4; i++)
#pragma unroll
        for (int j = 0; j < 4; j++)
#pragma unroll
            for (int r = 0; r < 4; r++) acc[i][j][r] = 0.f;

    float4 pa[4], pb[4];
#pragma unroll
    for (int i = 0; i < 4; i++) {
        pa[i] = *(const float4*)(Ap + (size_t)(32 * i) * K);
        pb[i] = *(const float4*)(Bp + (size_t)(32 * i) * K);
    }

    for (int kt = 0; kt < K; kt += TBK) {
#pragma unroll
        for (int i = 0; i < 4; i++) {
            unsigned* d = &As[(rl + 32 * i) * TST + kq];
            d[0] = f2tf(pa[i].x); d[1] = f2tf(pa[i].y);
            d[2] = f2tf(pa[i].z); d[3] = f2tf(pa[i].w);
            unsigned* e = &Bs[(rl + 32 * i) * TST + kq];
            e[0] = f2tf(pb[i].x); e[1] = f2tf(pb[i].y);
            e[2] = f2tf(pb[i].z); e[3] = f2tf(pb[i].w);
        }
        __syncthreads();

        if (kt + TBK < K) {
#pragma unroll
            for (int i = 0; i < 4; i++) {
                pa[i] = *(const float4*)(Ap + (size_t)(32 * i) * K + kt + TBK);
                pb[i] = *(const float4*)(Bp + (size_t)(32 * i) * K + kt + TBK);
            }
        }

#pragma unroll
        for (int ks = 0; ks < 4; ks++) {
            const int k0 = ks * 8;
            unsigned a[4][4], b[4][2];
#pragma unroll
            for (int im = 0; im < 4; im++) {
                const unsigned* p = &As[(wm * 64 + im * 16 + g) * TST + k0 + t];
                a[im][0] = p[0];
                a[im][1] = p[8 * TST];
                a[im][2] = p[4];
                a[im][3] = p[8 * TST + 4];
            }
#pragma unroll
            for (int jn = 0; jn < 4; jn++) {
                const unsigned* p = &Bs[(wn * 32 + jn * 8 + g) * TST + k0 + t];
                b[jn][0] = p[0];
                b[jn][1] = p[4];
            }
#pragma unroll
            for (int im = 0; im < 4; im++)
#pragma unroll
                for (int jn = 0; jn < 4; jn++) mma_tf32(acc[im][jn], a[im], b[jn]);
        }
        __syncthreads();
    }

#pragma unroll
    for (int im = 0; im < 4; im++) {
        const int r0 = bm + wm * 64 + im * 16 + g;
#pragma unroll
        for (int jn = 0; jn < 4; jn++) {
            const int c0 = bn + wn * 32 + jn * 8 + 2 * t;
            *(float2*)&C[(size_t)r0 * N + c0] =
                make_float2(acc[im][jn][0], acc[im][jn][1]);
            *(float2*)&C[(size_t)(r0 + 8) * N + c0] =
                make_float2(acc[im][jn][2], acc[im][jn][3]);
        }
    }
}

// ---------------------------------------------------------------------------
// Flash attention, tf32 mma. Block = 256 threads (8 warps), 128 q rows/block,
// warp w owns q rows [w*16, w*16+16). KV tile = 64. Each warp computes full
// 16x64 score rows -> softmax is warp-local (shfl over 4-lane t-group).
// Strides: Qs/Ks/Ps=68 (4g+t CF), Vs=72 (8t+g CF for the B-operand pattern).
// ---------------------------------------------------------------------------
#define FQ 128
#define FK 64
#define QST 68
#define KST 68
#define VST 72
#define PST 68
#define QS_OFF 0
#define KS_OFF (FQ * QST)
#define VS_OFF (KS_OFF + FK * KST)
#define PS_OFF (VS_OFF + FK * VST)
#define FL_WORDS (PS_OFF + FQ * PST)
#define FL_SMEM (FL_WORDS * 4)

__global__ __launch_bounds__(256)
void flash_tf32(const float* __restrict__ qkv, float* __restrict__ attn) {
    extern __shared__ unsigned sm[];
    unsigned* Qs = sm + QS_OFF;
    unsigned* Ks = sm + KS_OFF;
    unsigned* Vs = sm + VS_OFF;
    unsigned* Ps = sm + PS_OFF;

    const int qb = blockIdx.x * FQ;
    const int h = blockIdx.y, b = blockIdx.z;
    const int tid = threadIdx.x;
    const int wid = tid >> 5, lane = tid & 31;
    const int g = lane >> 2, t = lane & 3;
    const int wq = wid * 16;

    const size_t rs = QKV_COLS;
    const float* qg = qkv + (size_t)(b * SEQ + qb) * rs + h * HD;
    const float* kg = qkv + (size_t)(b * SEQ) * rs + HID + h * HD;
    const float* vg = qkv + (size_t)(b * SEQ) * rs + 2 * HID + h * HD;

    // Load Q tile, fold in softmax scale 1/8
    for (int e = tid; e < FQ * 16; e += 256) {
        int r = e >> 4, c = (e & 15) * 4;
        float4 v = *(const float4*)(qg + (size_t)r * rs + c);
        unsigned* d = &Qs[r * QST + c];
        d[0] = f2tf(v.x * 0.125f); d[1] = f2tf(v.y * 0.125f);
        d[2] = f2tf(v.z * 0.125f); d[3] = f2tf(v.w * 0.125f);
    }

    float o[8][4];
    float m0 = -1e30f, m1 = -1e30f, l0 = 0.f, l1 = 0.f;
#pragma unroll
    for (int j = 0; j < 8; j++)
#pragma unroll
        for (int r = 0; r < 4; r++) o[j][r] = 0.f;

    for (int kb = 0; kb < SEQ; kb += FK) {
        __syncthreads();  // prev iter's K/V reads done; also orders Q load
        for (int e = tid; e < FK * 16; e += 256) {
            int r = e >> 4, c = (e & 15) * 4;
            float4 kv = *(const float4*)(kg + (size_t)(kb + r) * rs + c);
            unsigned* d = &Ks[r * KST + c];
            d[0] = f2tf(kv.x); d[1] = f2tf(kv.y);
            d[2] = f2tf(kv.z); d[3] = f2tf(kv.w);
            float4 vv = *(const float4*)(vg + (size_t)(kb + r) * rs + c);
            unsigned* e2 = &Vs[r * VST + c];
            e2[0] = f2tf(vv.x); e2[1] = f2tf(vv.y);
            e2[2] = f2tf(vv.z); e2[3] = f2tf(vv.w);
        }
        __syncthreads();

        // S = Q @ K^T  (16 rows x 64 cols per warp)
        float s[8][4];
#pragma unroll
        for (int j = 0; j < 8; j++)
#pragma unroll
            for (int r = 0; r < 4; r++) s[j][r] = 0.f;
#pragma unroll
        for (int ks = 0; ks < 8; ks++) {
            const int k0 = ks * 8;
            unsigned a[4];
            const unsigned* p = &Qs[(wq + g) * QST + k0 + t];
            a[0] = p[0]; a[1] = p[8 * QST]; a[2] = p[4]; a[3] = p[8 * QST + 4];
#pragma unroll
            for (int jn = 0; jn < 8; jn++) {
                unsigned bb[2];
                const unsigned* q = &Ks[(jn * 8 + g) * KST + k0 + t];
                bb[0] = q[0]; bb[1] = q[4];
                mma_tf32(s[jn], a, bb);
            }
        }

        // Online softmax (rows g and g+8 of this warp's 16 rows)
        float rm0 = -1e30f, rm1 = -1e30f;
#pragma unroll
        for (int j = 0; j < 8; j++) {
            rm0 = fmaxf(rm0, fmaxf(s[j][0], s[j][1]));
            rm1 = fmaxf(rm1, fmaxf(s[j][2], s[j][3]));
        }
        rm0 = fmaxf(rm0, __shfl_xor_sync(0xffffffffu, rm0, 1));
        rm0 = fmaxf(rm0, __shfl_xor_sync(0xffffffffu, rm0, 2));
        rm1 = fmaxf(rm1, __shfl_xor_sync(0xffffffffu, rm1, 1));
        rm1 = fmaxf(rm1, __shfl_xor_sync(0xffffffffu, rm1, 2));
        const float mn0 = fmaxf(m0, rm0), mn1 = fmaxf(m1, rm1);
        const float cr0 = __expf(m0 - mn0), cr1 = __expf(m1 - mn1);
        m0 = mn0; m1 = mn1;
        float sum0 = 0.f, sum1 = 0.f;
#pragma unroll
        for (int j = 0; j < 8; j++) {
            s[j][0] = __expf(s[j][0] - mn0);
            s[j][1] = __expf(s[j][1] - mn0);
            s[j][2] = __expf(s[j][2] - mn1);
            s[j][3] = __expf(s[j][3] - mn1);
            sum0 += s[j][0] + s[j][1];
            sum1 += s[j][2] + s[j][3];
        }
        sum0 += __shfl_xor_sync(0xffffffffu, sum0, 1);
        sum0 += __shfl_xor_sync(0xffffffffu, sum0, 2);
        sum1 += __shfl_xor_sync(0xffffffffu, sum1, 1);
        sum1 += __shfl_xor_sync(0xffffffffu, sum1, 2);
        l0 = l0 * cr0 + sum0;
        l1 = l1 * cr1 + sum1;
#pragma unroll
        for (int j = 0; j < 8; j++) {
            o[j][0] *= cr0; o[j][1] *= cr0;
            o[j][2] *= cr1; o[j][3] *= cr1;
        }

        // Stage P (tf32) into this warp's own rows of Ps
#pragma unroll
        for (int j = 0; j < 8; j++) {
            *(uint2*)&Ps[(wq + g) * PST + j * 8 + 2 * t] =
                make_uint2(f2tf(s[j][0]), f2tf(s[j][1]));
            *(uint2*)&Ps[(wq + g + 8) * PST + j * 8 + 2 * t] =
                make_uint2(f2tf(s[j][2]), f2tf(s[j][3]));
        }
        __syncwarp();

        // O += P @ V
#pragma unroll
        for (int ks = 0; ks < 8; ks++) {
            const int k0 = ks * 8;
            unsigned a[4];
            const unsigned* p = &Ps[(wq + g) * PST + k0 + t];
            a[0] = p[0]; a[1] = p[8 * PST]; a[2] = p[4]; a[3] = p[8 * PST + 4];
#pragma unroll
            for (int jn = 0; jn < 8; jn++) {
                unsigned bb[2];
                bb[0] = Vs[(k0 + t) * VST + jn * 8 + g];
                bb[1] = Vs[(k0 + t + 4) * VST + jn * 8 + g];
                mma_tf32(o[jn], a, bb);
            }
        }
        __syncwarp();  // protect Ps before next iteration's rewrite
    }

    const float inv0 = 1.f / l0, inv1 = 1.f / l1;
    float* outp = attn + (size_t)(b * SEQ + qb + wq + g) * HID + h * HD;
#pragma unroll
    for (int jn = 0; jn < 8; jn++) {
        *(float2*)&outp[jn * 8 + 2 * t] =
            make_float2(o[jn][0] * inv0, o[jn][1] * inv0);
        *(float2*)&outp[(size_t)8 * HID + jn * 8 + 2 * t] =
            make_float2(o[jn][2] * inv1, o[jn][3] * inv1);
    }
}

// ---------------------------------------------------------------------------
extern "C" void kernel_launch(void* const* d_in, const int* in_sizes, int n_in,
                              void* d_out, int out_size) {
    const float* hidden = (const float*)d_in[0];   // [2,2048,1024]
    const float* w_qkv  = (const float*)d_in[1];   // [3072,1024]
    const float* w_o    = (const float*)d_in[2];   // [1024,1024]
    float* out = (float*)d_out;                    // [2,2048,1024]

    float* qkv_ptr = nullptr;
    float* attn_ptr = nullptr;
    cudaGetSymbolAddress((void**)&qkv_ptr, g_qkv);
    cudaGetSymbolAddress((void**)&attn_ptr, g_attn);

    static bool attr_set = false;
    if (!attr_set) {
        cudaFuncSetAttribute(flash_tf32,
                             cudaFuncAttributeMaxDynamicSharedMemorySize,
                             FL_SMEM);
        attr_set = true;
    }

    // 1) QKV projection: [4096,1024] @ [3072,1024]^T -> [4096,3072]
    {
        dim3 grid(QKV_COLS / TBN, ROWS / TBM);
        gemm_tf32<<<grid, 256>>>(hidden, w_qkv, qkv_ptr, ROWS, QKV_COLS, HID);
    }

    // 2) Flash attention -> g_attn [B,S,H]
    {
        dim3 grid(SEQ / FQ, NH, BATCH);
        flash_tf32<<<grid, 256, FL_SMEM>>>(qkv_ptr, attn_ptr);
    }

    // 3) Output projection: [4096,1024] @ [1024,1024]^T -> [4096,1024]
    {
        dim3 grid(HID / TBN, ROWS / TBM);
        gemm_tf32<<<grid, 256>>>(attn_ptr, w_o, out, ROWS, HID, HID);
    }
}

// round 5
// speedup vs baseline: 2.8750x; 1.0491x over previous
#include <cuda_runtime.h>
#include <math.h>

// Problem constants: B=2, S=2048, H=1024, nh=16, hd=64
#define BATCH 2
#define SEQ   2048
#define HID   1024
#define NH    16
#define HD    64
#define ROWS  (BATCH * SEQ)        // 4096
#define QKV_COLS (3 * HID)         // 3072

__device__ float g_qkv[ROWS * QKV_COLS];
__device__ float g_attn[ROWS * HID];

// ---------------------------------------------------------------------------
// TF32 helpers
// ---------------------------------------------------------------------------
__device__ __forceinline__ unsigned f2tf(float x) {
    unsigned u;
    asm("cvt.rna.tf32.f32 %0, %1;" : "=r"(u) : "f"(x));
    return u;
}

__device__ __forceinline__ void mma_tf32(float c[4], const unsigned a[4],
                                         const unsigned b[2]) {
    asm volatile(
        "mma.sync.aligned.m16n8k8.row.col.f32.tf32.tf32.f32 "
        "{%0,%1,%2,%3}, {%4,%5,%6,%7}, {%8,%9}, {%0,%1,%2,%3};\n"
        : "+f"(c[0]), "+f"(c[1]), "+f"(c[2]), "+f"(c[3])
        : "r"(a[0]), "r"(a[1]), "r"(a[2]), "r"(a[3]), "r"(b[0]), "r"(b[1]));
}

// ---------------------------------------------------------------------------
// GEMM: C[M,N] = A[M,K] @ B[N,K]^T, tf32 tensor cores.
// Block 128x128x32, 256 threads = 8 warps (2m x 4n), warp tile 64x32.
// Double-buffered smem (dynamic, 73.7KB), ONE __syncthreads per K-iter.
// smem stride 36 words: fragment LDS addr = 36g + t == 4g+t (mod 32), CF.
// ---------------------------------------------------------------------------
#define TBM 128
#define TBN 128
#define TBK 32
#define TST 36
#define GEMM_SMEM (4 * TBM * TST * 4)   // 2 stages x (A + B)

__global__ __launch_bounds__(256, 1)
void gemm_tf32(const float* __restrict__ A, const float* __restrict__ B,
               float* __restrict__ C, int M, int N, int K) {
    extern __shared__ unsigned gsm[];
    unsigned* Asm = gsm;                     // [2][TBM*TST]
    unsigned* Bsm = gsm + 2 * TBM * TST;     // [2][TBN*TST]

    const int bm = blockIdx.y * TBM, bn = blockIdx.x * TBN;
    const int tid = threadIdx.x;
    const int rl = tid >> 3;          // load row 0..31
    const int kq = (tid & 7) * 4;     // load k quad
    const float* Ap = A + (size_t)(bm + rl) * K + kq;
    const float* Bp = B + (size_t)(bn + rl) * K + kq;

    const int wid = tid >> 5, lane = tid & 31;
    const int wm = wid & 1, wn = wid >> 1;
    const int g = lane >> 2, t = lane & 3;

    float acc[4][4][4];
#pragma unroll
    for (int i = 0; i < 4; i++)
#pragma unroll
        for (int j = 0; j < 4; j++)
#pragma unroll
            for (int r = 0; r < 4; r++) acc[i][j][r] = 0.f;

    // Prologue: prefetch tile 0
    float4 pa[4], pb[4];
#pragma unroll
    for (int i = 0; i < 4; i++) {
        pa[i] = *(const float4*)(Ap + (size_t)(32 * i) * K);
        pb[i] = *(const float4*)(Bp + (size_t)(32 * i) * K);
    }

    const int nst = K / TBK;
    for (int it = 0; it < nst; it++) {
        unsigned* As = Asm + (it & 1) * (TBM * TST);
        unsigned* Bs = Bsm + (it & 1) * (TBN * TST);

        // Convert + packed store of the prefetched tile
#pragma unroll
        for (int i = 0; i < 4; i++) {
            uint4 ua, ub;
            ua.x = f2tf(pa[i].x); ua.y = f2tf(pa[i].y);
            ua.z = f2tf(pa[i].z); ua.w = f2tf(pa[i].w);
            ub.x = f2tf(pb[i].x); ub.y = f2tf(pb[i].y);
            ub.z = f2tf(pb[i].z); ub.w = f2tf(pb[i].w);
            *(uint4*)&As[(rl + 32 * i) * TST + kq] = ua;
            *(uint4*)&Bs[(rl + 32 * i) * TST + kq] = ub;
        }

        // Prefetch next tile (overlaps with compute below)
        if (it + 1 < nst) {
            const int ko = (it + 1) * TBK;
#pragma unroll
            for (int i = 0; i < 4; i++) {
                pa[i] = *(const float4*)(Ap + (size_t)(32 * i) * K + ko);
                pb[i] = *(const float4*)(Bp + (size_t)(32 * i) * K + ko);
            }
        }
        __syncthreads();

#pragma unroll
        for (int ks = 0; ks < 4; ks++) {
            const int k0 = ks * 8;
            unsigned a[4][4], b[4][2];
#pragma unroll
            for (int im = 0; im < 4; im++) {
                const unsigned* p = &As[(wm * 64 + im * 16 + g) * TST + k0 + t];
                a[im][0] = p[0];
                a[im][1] = p[8 * TST];
                a[im][2] = p[4];
                a[im][3] = p[8 * TST + 4];
            }
#pragma unroll
            for (int jn = 0; jn < 4; jn++) {
                const unsigned* p = &Bs[(wn * 32 + jn * 8 + g) * TST + k0 + t];
                b[jn][0] = p[0];
                b[jn][1] = p[4];
            }
#pragma unroll
            for (int im = 0; im < 4; im++)
#pragma unroll
                for (int jn = 0; jn < 4; jn++) mma_tf32(acc[im][jn], a[im], b[jn]);
        }
        // No trailing sync: next iter writes the OTHER stage; writes to THIS
        // stage (it+2) happen only after all warps pass sync(it+1), which is
        // after every warp finished this compute.
    }

#pragma unroll
    for (int im = 0; im < 4; im++) {
        const int r0 = bm + wm * 64 + im * 16 + g;
#pragma unroll
        for (int jn = 0; jn < 4; jn++) {
            const int c0 = bn + wn * 32 + jn * 8 + 2 * t;
            *(float2*)&C[(size_t)r0 * N + c0] =
                make_float2(acc[im][jn][0], acc[im][jn][1]);
            *(float2*)&C[(size_t)(r0 + 8) * N + c0] =
                make_float2(acc[im][jn][2], acc[im][jn][3]);
        }
    }
}

// ---------------------------------------------------------------------------
// Flash attention, tf32 mma. 256 threads (8 warps), 128 q rows/block, warp w
// owns q rows [w*16, w*16+16); KV tile 64, double-buffered; ONE block sync
// per KV tile. Softmax is warp-local (shfl over 4-lane t-groups).
// Strides: Qs/Ks/Ps=68 (4g+t CF), Vs=72 (8t+g CF for B-operand pattern).
// ---------------------------------------------------------------------------
#define FQ 128
#define FK 64
#define QST 68
#define KST 68
#define VST 72
#define PST 68
#define QS_OFF 0
#define KS_OFF (FQ * QST)                       // 2 stages of K
#define VS_OFF (KS_OFF + 2 * FK * KST)          // 2 stages of V
#define PS_OFF (VS_OFF + 2 * FK * VST)
#define FL_WORDS (PS_OFF + FQ * PST)
#define FL_SMEM (FL_WORDS * 4)

__global__ __launch_bounds__(256)
void flash_tf32(const float* __restrict__ qkv, float* __restrict__ attn) {
    extern __shared__ unsigned sm[];
    unsigned* Qs = sm + QS_OFF;
    unsigned* Ps = sm + PS_OFF;

    const int qb = blockIdx.x * FQ;
    const int h = blockIdx.y, b = blockIdx.z;
    const int tid = threadIdx.x;
    const int wid = tid >> 5, lane = tid & 31;
    const int g = lane >> 2, t = lane & 3;
    const int wq = wid * 16;

    const size_t rs = QKV_COLS;
    const float* qg = qkv + (size_t)(b * SEQ + qb) * rs + h * HD;
    const float* kg = qkv + (size_t)(b * SEQ) * rs + HID + h * HD;
    const float* vg = qkv + (size_t)(b * SEQ) * rs + 2 * HID + h * HD;

    // KV loader geometry: thread covers rows rb+16k (k=0..3), col quad cc.
    const int rb = tid >> 4;
    const int cc = (tid & 15) * 4;

    // Load Q tile, fold in softmax scale 1/8
    for (int e = tid; e < FQ * 16; e += 256) {
        int r = e >> 4, c = (e & 15) * 4;
        float4 v = *(const float4*)(qg + (size_t)r * rs + c);
        uint4 u;
        u.x = f2tf(v.x * 0.125f); u.y = f2tf(v.y * 0.125f);
        u.z = f2tf(v.z * 0.125f); u.w = f2tf(v.w * 0.125f);
        *(uint4*)&Qs[r * QST + c] = u;
    }

    float o[8][4];
    float m0 = -1e30f, m1 = -1e30f, l0 = 0.f, l1 = 0.f;
#pragma unroll
    for (int j = 0; j < 8; j++)
#pragma unroll
        for (int r = 0; r < 4; r++) o[j][r] = 0.f;

    // Prologue: prefetch KV tile 0
    float4 pk[4], pv[4];
#pragma unroll
    for (int k = 0; k < 4; k++) {
        pk[k] = *(const float4*)(kg + (size_t)(rb + 16 * k) * rs + cc);
        pv[k] = *(const float4*)(vg + (size_t)(rb + 16 * k) * rs + cc);
    }

    const int ntiles = SEQ / FK;
    for (int it = 0; it < ntiles; it++) {
        unsigned* Ks = sm + KS_OFF + (it & 1) * (FK * KST);
        unsigned* Vs = sm + VS_OFF + (it & 1) * (FK * VST);

        // Convert + packed store prefetched KV tile
#pragma unroll
        for (int k = 0; k < 4; k++) {
            uint4 uk, uv;
            uk.x = f2tf(pk[k].x); uk.y = f2tf(pk[k].y);
            uk.z = f2tf(pk[k].z); uk.w = f2tf(pk[k].w);
            uv.x = f2tf(pv[k].x); uv.y = f2tf(pv[k].y);
            uv.z = f2tf(pv[k].z); uv.w = f2tf(pv[k].w);
            *(uint4*)&Ks[(rb + 16 * k) * KST + cc] = uk;
            *(uint4*)&Vs[(rb + 16 * k) * VST + cc] = uv;
        }

        // Prefetch next KV tile
        if (it + 1 < ntiles) {
            const size_t ro = (size_t)(it + 1) * FK;
#pragma unroll
            for (int k = 0; k < 4; k++) {
                pk[k] = *(const float4*)(kg + (ro + rb + 16 * k) * rs + cc);
                pv[k] = *(const float4*)(vg + (ro + rb + 16 * k) * rs + cc);
            }
        }
        __syncthreads();

        // S = Q @ K^T  (16 rows x 64 cols per warp)
        float s[8][4];
#pragma unroll
        for (int j = 0; j < 8; j++)
#pragma unroll
            for (int r = 0; r < 4; r++) s[j][r] = 0.f;
#pragma unroll
        for (int ks = 0; ks < 8; ks++) {
            const int k0 = ks * 8;
            unsigned a[4];
            const unsigned* p = &Qs[(wq + g) * QST + k0 + t];
            a[0] = p[0]; a[1] = p[8 * QST]; a[2] = p[4]; a[3] = p[8 * QST + 4];
#pragma unroll
            for (int jn = 0; jn < 8; jn++) {
                unsigned bb[2];
                const unsigned* q = &Ks[(jn * 8 + g) * KST + k0 + t];
                bb[0] = q[0]; bb[1] = q[4];
                mma_tf32(s[jn], a, bb);
            }
        }

        // Online softmax (rows g and g+8 of this warp's 16 rows)
        float rm0 = -1e30f, rm1 = -1e30f;
#pragma unroll
        for (int j = 0; j < 8; j++) {
            rm0 = fmaxf(rm0, fmaxf(s[j][0], s[j][1]));
            rm1 = fmaxf(rm1, fmaxf(s[j][2], s[j][3]));
        }
        rm0 = fmaxf(rm0, __shfl_xor_sync(0xffffffffu, rm0, 1));
        rm0 = fmaxf(rm0, __shfl_xor_sync(0xffffffffu, rm0, 2));
        rm1 = fmaxf(rm1, __shfl_xor_sync(0xffffffffu, rm1, 1));
        rm1 = fmaxf(rm1, __shfl_xor_sync(0xffffffffu, rm1, 2));
        const float mn0 = fmaxf(m0, rm0), mn1 = fmaxf(m1, rm1);
        const float cr0 = __expf(m0 - mn0), cr1 = __expf(m1 - mn1);
        m0 = mn0; m1 = mn1;
        float sum0 = 0.f, sum1 = 0.f;
#pragma unroll
        for (int j = 0; j < 8; j++) {
            s[j][0] = __expf(s[j][0] - mn0);
            s[j][1] = __expf(s[j][1] - mn0);
            s[j][2] = __expf(s[j][2] - mn1);
            s[j][3] = __expf(s[j][3] - mn1);
            sum0 += s[j][0] + s[j][1];
            sum1 += s[j][2] + s[j][3];
        }
        sum0 += __shfl_xor_sync(0xffffffffu, sum0, 1);
        sum0 += __shfl_xor_sync(0xffffffffu, sum0, 2);
        sum1 += __shfl_xor_sync(0xffffffffu, sum1, 1);
        sum1 += __shfl_xor_sync(0xffffffffu, sum1, 2);
        l0 = l0 * cr0 + sum0;
        l1 = l1 * cr1 + sum1;
#pragma unroll
        for (int j = 0; j < 8; j++) {
            o[j][0] *= cr0; o[j][1] *= cr0;
            o[j][2] *= cr1; o[j][3] *= cr1;
        }

        // Stage P (tf32) into this warp's private rows of Ps
#pragma unroll
        for (int j = 0; j < 8; j++) {
            *(uint2*)&Ps[(wq + g) * PST + j * 8 + 2 * t] =
                make_uint2(f2tf(s[j][0]), f2tf(s[j][1]));
            *(uint2*)&Ps[(wq + g + 8) * PST + j * 8 + 2 * t] =
                make_uint2(f2tf(s[j][2]), f2tf(s[j][3]));
        }
        __syncwarp();

        // O += P @ V
#pragma unroll
        for (int ks = 0; ks < 8; ks++) {
            const int k0 = ks * 8;
            unsigned a[4];
            const unsigned* p = &Ps[(wq + g) * PST + k0 + t];
            a[0] = p[0]; a[1] = p[8 * PST]; a[2] = p[4]; a[3] = p[8 * PST + 4];
#pragma unroll
            for (int jn = 0; jn < 8; jn++) {
                unsigned bb[2];
                bb[0] = Vs[(k0 + t) * VST + jn * 8 + g];
                bb[1] = Vs[(k0 + t + 4) * VST + jn * 8 + g];
                mma_tf32(o[jn], a, bb);
            }
        }
        __syncwarp();  // P reads done before next iter's P writes
    }

    const float inv0 = 1.f / l0, inv1 = 1.f / l1;
    float* outp = attn + (size_t)(b * SEQ + qb + wq + g) * HID + h * HD;
#pragma unroll
    for (int jn = 0; jn < 8; jn++) {
        *(float2*)&outp[jn * 8 + 2 * t] =
            make_float2(o[jn][0] * inv0, o[jn][1] * inv0);
        *(float2*)&outp[(size_t)8 * HID + jn * 8 + 2 * t] =
            make_float2(o[jn][2] * inv1, o[jn][3] * inv1);
    }
}

// ---------------------------------------------------------------------------
extern "C" void kernel_launch(void* const* d_in, const int* in_sizes, int n_in,
                              void* d_out, int out_size) {
    const float* hidden = (const float*)d_in[0];   // [2,2048,1024]
    const float* w_qkv  = (const float*)d_in[1];   // [3072,1024]
    const float* w_o    = (const float*)d_in[2];   // [1024,1024]
    float* out = (float*)d_out;                    // [2,2048,1024]

    float* qkv_ptr = nullptr;
    float* attn_ptr = nullptr;
    cudaGetSymbolAddress((void**)&qkv_ptr, g_qkv);
    cudaGetSymbolAddress((void**)&attn_ptr, g_attn);

    static bool attr_set = false;
    if (!attr_set) {
        cudaFuncSetAttribute(flash_tf32,
                             cudaFuncAttributeMaxDynamicSharedMemorySize,
                             FL_SMEM);
        cudaFuncSetAttribute(gemm_tf32,
                             cudaFuncAttributeMaxDynamicSharedMemorySize,
                             GEMM_SMEM);
        attr_set = true;
    }

    // 1) QKV projection: [4096,1024] @ [3072,1024]^T -> [4096,3072]
    {
        dim3 grid(QKV_COLS / TBN, ROWS / TBM);
        gemm_tf32<<<grid, 256, GEMM_SMEM>>>(hidden, w_qkv, qkv_ptr,
                                            ROWS, QKV_COLS, HID);
    }

    // 2) Flash attention -> g_attn [B,S,H]
    {
        dim3 grid(SEQ / FQ, NH, BATCH);
        flash_tf32<<<grid, 256, FL_SMEM>>>(qkv_ptr, attn_ptr);
    }

    // 3) Output projection: [4096,1024] @ [1024,1024]^T -> [4096,1024]
    {
        dim3 grid(HID / TBN, ROWS / TBM);
        gemm_tf32<<<grid, 256, GEMM_SMEM>>>(attn_ptr, w_o, out,
                                            ROWS, HID, HID);
    }
}

// round 7
// speedup vs baseline: 2.9222x; 1.0164x over previous
#include <cuda_runtime.h>
#include <cuda_fp16.h>
#include <math.h>
#include <cstdint>

// Problem constants: B=2, S=2048, H=1024, nh=16, hd=64
#define BATCH 2
#define SEQ   2048
#define HID   1024
#define NH    16
#define HD    64
#define ROWS  (BATCH * SEQ)        // 4096
#define QKV_COLS (3 * HID)         // 3072

// fp16 scratch (no allocations allowed)
__device__ __half g_hidden_h[ROWS * HID];
__device__ __half g_wqkv_h[QKV_COLS * HID];
__device__ __half g_wo_h[HID * HID];
__device__ __half g_qkv[ROWS * QKV_COLS];
__device__ __half g_attn[ROWS * HID];

// ---------------------------------------------------------------------------
// Helpers
// ---------------------------------------------------------------------------
__device__ __forceinline__ uint32_t smem_u32(const void* p) {
    uint32_t a;
    asm("{ .reg .u64 t; cvta.to.shared.u64 t, %1; cvt.u32.u64 %0, t; }"
        : "=r"(a) : "l"(p));
    return a;
}

__device__ __forceinline__ void mma_f16(float c[4], const unsigned a[4],
                                        const unsigned b[2]) {
    asm volatile(
        "mma.sync.aligned.m16n8k16.row.col.f32.f16.f16.f32 "
        "{%0,%1,%2,%3}, {%4,%5,%6,%7}, {%8,%9}, {%0,%1,%2,%3};\n"
        : "+f"(c[0]), "+f"(c[1]), "+f"(c[2]), "+f"(c[3])
        : "r"(a[0]), "r"(a[1]), "r"(a[2]), "r"(a[3]), "r"(b[0]), "r"(b[1]));
}

__device__ __forceinline__ void cp_async16(uint32_t dst, const void* src) {
    asm volatile("cp.async.ca.shared.global [%0], [%1], 16;\n"
                 :: "r"(dst), "l"(src));
}
#define CP_COMMIT() asm volatile("cp.async.commit_group;\n" ::: "memory")
#define CP_WAIT1()  asm volatile("cp.async.wait_group 1;\n" ::: "memory")

// ---------------------------------------------------------------------------
// fp32 -> fp16 convert (pre-pass). n divisible by 4.
// ---------------------------------------------------------------------------
__global__ void cvt_h(const float* __restrict__ in, __half* __restrict__ out) {
    int i = (blockIdx.x * blockDim.x + threadIdx.x) * 4;
    float4 v = *(const float4*)(in + i);
    *(__half2*)(out + i)     = __floats2half2_rn(v.x, v.y);
    *(__half2*)(out + i + 2) = __floats2half2_rn(v.z, v.w);
}

// ---------------------------------------------------------------------------
// fp16 GEMM: C[M,N] = A[M,K] @ B[N,K]^T (both K-contiguous, half).
// Block 128x128x32(halfs), 256 thr = 8 warps (2m x 4n), warp tile 64x32.
// 3-stage cp.async pipeline, smem row = 16 half2 data + 4 pad (stride 20):
// fragment LDS bank = (20g + t) mod 32 -> all 32 distinct, conflict-free.
// launch_bounds(256,2) -> 2 CTAs/SM.
// ---------------------------------------------------------------------------
#define GBM 128
#define GBN 128
#define GBK 32                      // halfs per K-tile
#define GS2 20                      // half2 words per smem row
#define G_STAGE_W (2 * GBM * GS2)   // words per stage (A then B)
#define G_NSTAGE 3
#define GEMM_SMEM (G_NSTAGE * G_STAGE_W * 4)   // 61440 B

__device__ __forceinline__ void gemm_issue(uint32_t sbase, int stage,
                                           const __half* Ag, const __half* Bg,
                                           int K, int kt, int tid) {
    const uint32_t st = sbase + stage * (G_STAGE_W * 4);
#pragma unroll
    for (int u = 0; u < 2; u++) {
        const int c = 2 * tid + u;          // 512 chunks of 16B per operand
        const int row = c >> 2, seg = c & 3;
        cp_async16(st + (row * GS2 + seg * 4) * 4,
                   Ag + (size_t)row * K + kt + seg * 8);
        cp_async16(st + (GBM * GS2 + row * GS2 + seg * 4) * 4,
                   Bg + (size_t)row * K + kt + seg * 8);
    }
}

template <bool HALF_OUT>
__global__ __launch_bounds__(256, 2)
void gemm_f16(const __half* __restrict__ A, const __half* __restrict__ B,
              void* __restrict__ Cv, int M, int N, int K) {
    extern __shared__ char smc[];
    const uint32_t sb = smem_u32(smc);
    const int tid = threadIdx.x;
    const int bm = blockIdx.y * GBM, bn = blockIdx.x * GBN;
    const int wid = tid >> 5, lane = tid & 31;
    const int wm = wid & 1, wn = wid >> 1;
    const int g = lane >> 2, t = lane & 3;
    const __half* Ag = A + (size_t)bm * K;
    const __half* Bg = B + (size_t)bn * K;

    float acc[4][4][4];
#pragma unroll
    for (int i = 0; i < 4; i++)
#pragma unroll
        for (int j = 0; j < 4; j++)
#pragma unroll
            for (int r = 0; r < 4; r++) acc[i][j][r] = 0.f;

    gemm_issue(sb, 0, Ag, Bg, K, 0, tid);
    CP_COMMIT();
    gemm_issue(sb, 1, Ag, Bg, K, GBK, tid);
    CP_COMMIT();

    const int NIT = K / GBK;
    for (int it = 0; it < NIT; it++) {
        CP_WAIT1();           // stage `it` landed
        __syncthreads();      // all warps past compute(it-1); smem visible

        // Refill slot (it+2)%3 (= stage it-1's slot, safe after the sync)
        if (it + 2 < NIT)
            gemm_issue(sb, (it + 2) % 3, Ag, Bg, K, (it + 2) * GBK, tid);
        CP_COMMIT();          // keep group count aligned even when empty

        const unsigned* Sw = (const unsigned*)(smc) + (it % 3) * G_STAGE_W;
        const unsigned* As = Sw;
        const unsigned* Bs = Sw + GBM * GS2;
#pragma unroll
        for (int ks = 0; ks < 2; ks++) {      // two k16 steps per 32-half tile
            unsigned a[4][4], b[4][2];
#pragma unroll
            for (int im = 0; im < 4; im++) {
                const unsigned* p = &As[(wm * 64 + im * 16 + g) * GS2 + ks * 8 + t];
                a[im][0] = p[0];
                a[im][1] = p[8 * GS2];
                a[im][2] = p[4];
                a[im][3] = p[8 * GS2 + 4];
            }
#pragma unroll
            for (int jn = 0; jn < 4; jn++) {
                const unsigned* p = &Bs[(wn * 32 + jn * 8 + g) * GS2 + ks * 8 + t];
                b[jn][0] = p[0];
                b[jn][1] = p[4];
            }
#pragma unroll
            for (int im = 0; im < 4; im++)
#pragma unroll
                for (int jn = 0; jn < 4; jn++) mma_f16(acc[im][jn], a[im], b[jn]);
        }
    }

#pragma unroll
    for (int im = 0; im < 4; im++) {
        const int r0 = bm + wm * 64 + im * 16 + g;
#pragma unroll
        for (int jn = 0; jn < 4; jn++) {
            const int c0 = bn + wn * 32 + jn * 8 + 2 * t;
            if (HALF_OUT) {
                __half* C = (__half*)Cv;
                *(__half2*)&C[(size_t)r0 * N + c0] =
                    __floats2half2_rn(acc[im][jn][0], acc[im][jn][1]);
                *(__half2*)&C[(size_t)(r0 + 8) * N + c0] =
                    __floats2half2_rn(acc[im][jn][2], acc[im][jn][3]);
            } else {
                float* C = (float*)Cv;
                *(float2*)&C[(size_t)r0 * N + c0] =
                    make_float2(acc[im][jn][0], acc[im][jn][1]);
                *(float2*)&C[(size_t)(r0 + 8) * N + c0] =
                    make_float2(acc[im][jn][2], acc[im][jn][3]);
            }
        }
    }
}

// ---------------------------------------------------------------------------
// Flash attention, fp16 m16n8k16. 256 thr (8 warps), 128 q rows/block, warp w
// owns q rows [16w,16w+16); KV tile 64, double-buffered; one block sync/tile.
// All smem rows: 32 half2 data + 4 pad (stride 36) -> bank (4g+t), CF.
// V stored transposed+pair-interleaved: Vt[d][kv2] = half2(V[2kv2][d],V[2kv2+1][d]).
// ---------------------------------------------------------------------------
#define FQ 128
#define FK 64
#define FS2 36                           // half2 stride for all flash tiles
#define FQS_OFF 0                        // Qs: 128*36
#define FKS_OFF (FQ * FS2)               // Ks: 2 stages x 64*36
#define FVT_OFF (FKS_OFF + 2 * FK * FS2) // Vt: 2 stages x 64*36
#define FPS_OFF (FVT_OFF + 2 * FK * FS2) // Ps: 128*36
#define FL_WORDS (FPS_OFF + FQ * FS2)
#define FL_SMEM (FL_WORDS * 4)           // 73728 B

__global__ __launch_bounds__(256, 2)
void flash_f16(const __half* __restrict__ qkv, __half* __restrict__ attn) {
    extern __shared__ unsigned sm[];
    unsigned* Qs = sm + FQS_OFF;
    unsigned* Ps = sm + FPS_OFF;

    const int qb = blockIdx.x * FQ;
    const int h = blockIdx.y, b = blockIdx.z;
    const int tid = threadIdx.x;
    const int wid = tid >> 5, lane = tid & 31;
    const int g = lane >> 2, t = lane & 3;
    const int wq = wid * 16;

    const size_t rs = QKV_COLS;
    const __half* qg = qkv + (size_t)(b * SEQ + qb) * rs + h * HD;
    const __half* kg = qkv + (size_t)(b * SEQ) * rs + HID + h * HD;
    const __half* vg = qkv + (size_t)(b * SEQ) * rs + 2 * HID + h * HD;

    // Q tile: 128 rows x 64 halfs = 1024 x 16B chunks, 4 per thread.
#pragma unroll
    for (int u = 0; u < 4; u++) {
        const int c = tid * 4 + u;
        const int row = c >> 3, seg = c & 7;
        uint4 v = *(const uint4*)(qg + (size_t)row * rs + seg * 8);
        *(uint4*)&Qs[row * FS2 + seg * 4] = v;
    }

    // K loader: 2 chunks/thread.  V loader: (kv pair, d-segment) per thread.
    const int kc0 = tid * 2;
    const int krow0 = kc0 >> 3, kseg0 = kc0 & 7;
    const int krow1 = (kc0 + 1) >> 3, kseg1 = (kc0 + 1) & 7;
    const int kv2 = tid & 31;          // pair of kv rows (2kv2, 2kv2+1)
    const int dseg = tid >> 5;         // 8 halfs of d per thread

    float o[8][4];
    float m0 = -1e30f, m1 = -1e30f, l0 = 0.f, l1 = 0.f;
#pragma unroll
    for (int j = 0; j < 8; j++)
#pragma unroll
        for (int r = 0; r < 4; r++) o[j][r] = 0.f;

    // Prologue: prefetch KV tile 0
    uint4 pk0 = *(const uint4*)(kg + (size_t)krow0 * rs + kseg0 * 8);
    uint4 pk1 = *(const uint4*)(kg + (size_t)krow1 * rs + kseg1 * 8);
    uint4 pv0 = *(const uint4*)(vg + (size_t)(2 * kv2) * rs + dseg * 8);
    uint4 pv1 = *(const uint4*)(vg + (size_t)(2 * kv2 + 1) * rs + dseg * 8);

    const int ntiles = SEQ / FK;
    for (int it = 0; it < ntiles; it++) {
        unsigned* Ks = sm + FKS_OFF + (it & 1) * (FK * FS2);
        unsigned* Vt = sm + FVT_OFF + (it & 1) * (FK * FS2);

        // STS K (linear, padded rows)
        *(uint4*)&Ks[krow0 * FS2 + kseg0 * 4] = pk0;
        *(uint4*)&Ks[krow1 * FS2 + kseg1 * 4] = pk1;
        // STS Vt (transpose + pair-interleave)
        {
            const __half* ev = (const __half*)&pv0;
            const __half* od = (const __half*)&pv1;
#pragma unroll
            for (int j = 0; j < 8; j++) {
                __half2 hp = __halves2half2(ev[j], od[j]);
                Vt[(dseg * 8 + j) * FS2 + kv2] = *(unsigned*)&hp;
            }
        }

        // Prefetch next tile
        if (it + 1 < ntiles) {
            const size_t ro = (size_t)(it + 1) * FK;
            pk0 = *(const uint4*)(kg + (ro + krow0) * rs + kseg0 * 8);
            pk1 = *(const uint4*)(kg + (ro + krow1) * rs + kseg1 * 8);
            pv0 = *(const uint4*)(vg + (ro + 2 * kv2) * rs + dseg * 8);
            pv1 = *(const uint4*)(vg + (ro + 2 * kv2 + 1) * rs + dseg * 8);
        }
        __syncthreads();

        // S = Q @ K^T (raw scores; softmax applies the 1/8 scale)
        float s[8][4];
#pragma unroll
        for (int j = 0; j < 8; j++)
#pragma unroll
            for (int r = 0; r < 4; r++) s[j][r] = 0.f;
#pragma unroll
        for (int ks = 0; ks < 4; ks++) {
            unsigned a[4];
            const unsigned* p = &Qs[(wq + g) * FS2 + ks * 8 + t];
            a[0] = p[0]; a[1] = p[8 * FS2]; a[2] = p[4]; a[3] = p[8 * FS2 + 4];
#pragma unroll
            for (int jn = 0; jn < 8; jn++) {
                unsigned bb[2];
                const unsigned* q = &Ks[(jn * 8 + g) * FS2 + ks * 8 + t];
                bb[0] = q[0]; bb[1] = q[4];
                mma_f16(s[jn], a, bb);
            }
        }

        // Online softmax on raw scores, scale folded into exp args
        float rm0 = -1e30f, rm1 = -1e30f;
#pragma unroll
        for (int j = 0; j < 8; j++) {
            rm0 = fmaxf(rm0, fmaxf(s[j][0], s[j][1]));
            rm1 = fmaxf(rm1, fmaxf(s[j][2], s[j][3]));
        }
        rm0 = fmaxf(rm0, __shfl_xor_sync(0xffffffffu, rm0, 1));
        rm0 = fmaxf(rm0, __shfl_xor_sync(0xffffffffu, rm0, 2));
        rm1 = fmaxf(rm1, __shfl_xor_sync(0xffffffffu, rm1, 1));
        rm1 = fmaxf(rm1, __shfl_xor_sync(0xffffffffu, rm1, 2));
        const float mn0 = fmaxf(m0, rm0), mn1 = fmaxf(m1, rm1);
        const float cr0 = __expf((m0 - mn0) * 0.125f);
        const float cr1 = __expf((m1 - mn1) * 0.125f);
        m0 = mn0; m1 = mn1;
        float sum0 = 0.f, sum1 = 0.f;
#pragma unroll
        for (int j = 0; j < 8; j++) {
            s[j][0] = __expf((s[j][0] - mn0) * 0.125f);
            s[j][1] = __expf((s[j][1] - mn0) * 0.125f);
            s[j][2] = __expf((s[j][2] - mn1) * 0.125f);
            s[j][3] = __expf((s[j][3] - mn1) * 0.125f);
            sum0 += s[j][0] + s[j][1];
            sum1 += s[j][2] + s[j][3];
        }
        sum0 += __shfl_xor_sync(0xffffffffu, sum0, 1);
        sum0 += __shfl_xor_sync(0xffffffffu, sum0, 2);
        sum1 += __shfl_xor_sync(0xffffffffu, sum1, 1);
        sum1 += __shfl_xor_sync(0xffffffffu, sum1, 2);
        l0 = l0 * cr0 + sum0;
        l1 = l1 * cr1 + sum1;
#pragma unroll
        for (int j = 0; j < 8; j++) {
            o[j][0] *= cr0; o[j][1] *= cr0;
            o[j][2] *= cr1; o[j][3] *= cr1;
        }

        // Stage P as fp16 in this warp's private rows
#pragma unroll
        for (int j = 0; j < 8; j++) {
            __half2 h0 = __floats2half2_rn(s[j][0], s[j][1]);
            __half2 h1 = __floats2half2_rn(s[j][2], s[j][3]);
            Ps[(wq + g) * FS2 + j * 4 + t] = *(unsigned*)&h0;
            Ps[(wq + g + 8) * FS2 + j * 4 + t] = *(unsigned*)&h1;
        }
        __syncwarp();

        // O += P @ V
#pragma unroll
        for (int ks = 0; ks < 4; ks++) {
            unsigned a[4];
            const unsigned* p = &Ps[(wq + g) * FS2 + ks * 8 + t];
            a[0] = p[0]; a[1] = p[8 * FS2]; a[2] = p[4]; a[3] = p[8 * FS2 + 4];
#pragma unroll
            for (int jn = 0; jn < 8; jn++) {
                unsigned bb[2];
                const unsigned* q = &Vt[(jn * 8 + g) * FS2 + ks * 8 + t];
                bb[0] = q[0]; bb[1] = q[4];
                mma_f16(o[jn], a, bb);
            }
        }
        __syncwarp();  // P reads done before next iter's P writes
    }

    const float inv0 = 1.f / l0, inv1 = 1.f / l1;
    __half2* out0 = (__half2*)attn + (size_t)(b * SEQ + qb + wq + g) * (HID / 2)
                    + h * (HD / 2);
    __half2* out1 = out0 + (size_t)8 * (HID / 2);
#pragma unroll
    for (int jn = 0; jn < 8; jn++) {
        out0[jn * 4 + t] = __floats2half2_rn(o[jn][0] * inv0, o[jn][1] * inv0);
        out1[jn * 4 + t] = __floats2half2_rn(o[jn][2] * inv1, o[jn][3] * inv1);
    }
}

// ---------------------------------------------------------------------------
extern "C" void kernel_launch(void* const* d_in, const int* in_sizes, int n_in,
                              void* d_out, int out_size) {
    const float* hidden = (const float*)d_in[0];   // [2,2048,1024]
    const float* w_qkv  = (const float*)d_in[1];   // [3072,1024]
    const float* w_o    = (const float*)d_in[2];   // [1024,1024]
    float* out = (float*)d_out;                    // [2,2048,1024]

    __half *hid_h, *wqkv_h, *wo_h, *qkv_h, *attn_h;
    cudaGetSymbolAddress((void**)&hid_h, g_hidden_h);
    cudaGetSymbolAddress((void**)&wqkv_h, g_wqkv_h);
    cudaGetSymbolAddress((void**)&wo_h, g_wo_h);
    cudaGetSymbolAddress((void**)&qkv_h, g_qkv);
    cudaGetSymbolAddress((void**)&attn_h, g_attn);

    static bool attr_set = false;
    if (!attr_set) {
        cudaFuncSetAttribute(gemm_f16<true>,
                             cudaFuncAttributeMaxDynamicSharedMemorySize,
                             GEMM_SMEM);
        cudaFuncSetAttribute(gemm_f16<false>,
                             cudaFuncAttributeMaxDynamicSharedMemorySize,
                             GEMM_SMEM);
        cudaFuncSetAttribute(flash_f16,
                             cudaFuncAttributeMaxDynamicSharedMemorySize,
                             FL_SMEM);
        attr_set = true;
    }

    // 0) fp32 -> fp16 pre-convert of the three inputs
    cvt_h<<<(ROWS * HID) / 1024, 256>>>(hidden, hid_h);
    cvt_h<<<(QKV_COLS * HID) / 1024, 256>>>(w_qkv, wqkv_h);
    cvt_h<<<(HID * HID) / 1024, 256>>>(w_o, wo_h);

    // 1) QKV projection -> g_qkv (half): [4096,1024] @ [3072,1024]^T
    {
        dim3 grid(QKV_COLS / GBN, ROWS / GBM);   // (24, 32)
        gemm_f16<true><<<grid, 256, GEMM_SMEM>>>(hid_h, wqkv_h, qkv_h,
                                                 ROWS, QKV_COLS, HID);
    }

    // 2) Flash attention -> g_attn (half), [B,S,H] layout
    {
        dim3 grid(SEQ / FQ, NH, BATCH);          // (16, 16, 2)
        flash_f16<<<grid, 256, FL_SMEM>>>(qkv_h, attn_h);
    }

    // 3) Output projection -> fp32 out: [4096,1024] @ [1024,1024]^T
    {
        dim3 grid(HID / GBN, ROWS / GBM);        // (8, 32)
        gemm_f16<false><<<grid, 256, GEMM_SMEM>>>(attn_h, wo_h, out,
                                                  ROWS, HID, HID);
    }
}

// round 10
// speedup vs baseline: 5.0489x; 1.7278x over previous
#include <cuda_runtime.h>
#include <cuda_fp16.h>
#include <math.h>
#include <cstdint>

// Problem constants: B=2, S=2048, H=1024, nh=16, hd=64
#define BATCH 2
#define SEQ   2048
#define HID   1024
#define NH    16
#define HD    64
#define ROWS  (BATCH * SEQ)        // 4096
#define QKV_COLS (3 * HID)         // 3072

// fp16 scratch (no allocations allowed)
__device__ __half g_hidden_h[ROWS * HID];
__device__ __half g_wqkv_h[QKV_COLS * HID];
__device__ __half g_wo_h[HID * HID];
__device__ __half g_qkv[ROWS * QKV_COLS];
__device__ __half g_attn[ROWS * HID];

// ---------------------------------------------------------------------------
// Helpers
// ---------------------------------------------------------------------------
__device__ __forceinline__ uint32_t smem_u32(const void* p) {
    uint32_t a;
    asm("{ .reg .u64 t; cvta.to.shared.u64 t, %1; cvt.u32.u64 %0, t; }"
        : "=r"(a) : "l"(p));
    return a;
}

__device__ __forceinline__ void mma_f16(float c[4], const unsigned a[4],
                                        const unsigned b[2]) {
    asm volatile(
        "mma.sync.aligned.m16n8k16.row.col.f32.f16.f16.f32 "
        "{%0,%1,%2,%3}, {%4,%5,%6,%7}, {%8,%9}, {%0,%1,%2,%3};\n"
        : "+f"(c[0]), "+f"(c[1]), "+f"(c[2]), "+f"(c[3])
        : "r"(a[0]), "r"(a[1]), "r"(a[2]), "r"(a[3]), "r"(b[0]), "r"(b[1]));
}

__device__ __forceinline__ void ldsm4(unsigned r[4], uint32_t addr) {
    asm volatile(
        "ldmatrix.sync.aligned.m8n8.x4.shared.b16 {%0,%1,%2,%3}, [%4];"
        : "=r"(r[0]), "=r"(r[1]), "=r"(r[2]), "=r"(r[3]) : "r"(addr));
}

__device__ __forceinline__ void cp_async16(uint32_t dst, const void* src) {
    asm volatile("cp.async.cg.shared.global [%0], [%1], 16;\n"
                 :: "r"(dst), "l"(src));
}
#define CP_COMMIT() asm volatile("cp.async.commit_group;\n" ::: "memory")
#define CP_WAIT2()  asm volatile("cp.async.wait_group 2;\n" ::: "memory")

__device__ __forceinline__ unsigned packh2(float x, float y) {
    __half2 h = __floats2half2_rn(x, y);
    return *(unsigned*)&h;
}

// ---------------------------------------------------------------------------
// fp32 -> fp16 convert (pre-pass)
// ---------------------------------------------------------------------------
__global__ void cvt_h(const float* __restrict__ in, __half* __restrict__ out) {
    int i = (blockIdx.x * blockDim.x + threadIdx.x) * 4;
    float4 v = *(const float4*)(in + i);
    *(__half2*)(out + i)     = __floats2half2_rn(v.x, v.y);
    *(__half2*)(out + i + 2) = __floats2half2_rn(v.z, v.w);
}

// ---------------------------------------------------------------------------
// fp16 GEMM: C[M,N] = A[M,K] @ B[N,K]^T (both K-contiguous, half).
// Block 128x256x32(halfs), 256 thr = 8 warps (2m x 4n), warp tile 64x64.
// 4-stage cp.async pipeline. smem row = 32 halfs data + 8 pad (80B, 16x5):
// ldmatrix rows 80B apart hit 8 distinct 16B banks -> conflict-free.
// 1 CTA/SM; latency hidden by 32 independent acc chains/warp + ldmatrix.
// ---------------------------------------------------------------------------
#define GBM 128
#define GBN 256
#define GBK 32
#define GROW 40                              // halfs per padded row
#define G_STAGE_H ((GBM + GBN) * GROW)       // 15360 halfs / stage
#define G_NST 4
#define GEMM_SMEM (G_NST * G_STAGE_H * 2)    // 122880 B

__device__ __forceinline__ void gemm_issue(uint32_t sbase, int stage,
                                           const __half* Ag, const __half* Bg,
                                           int K, int kt, int tid) {
    const uint32_t st = sbase + stage * (G_STAGE_H * 2);
    // A: 512 chunks of 16B, 2/thread
    {
        const int row = tid >> 1;
        const int sg0 = (tid & 1) * 2;
        cp_async16(st + row * 80 + sg0 * 16,
                   Ag + (size_t)row * K + kt + sg0 * 8);
        cp_async16(st + row * 80 + (sg0 + 1) * 16,
                   Ag + (size_t)row * K + kt + (sg0 + 1) * 8);
    }
    // B: 1024 chunks of 16B, 4/thread (row = tid)
    {
        const uint32_t bs = st + GBM * 80;
#pragma unroll
        for (int u = 0; u < 4; u++)
            cp_async16(bs + tid * 80 + u * 16,
                       Bg + (size_t)tid * K + kt + u * 8);
    }
}

template <bool HALF_OUT>
__global__ __launch_bounds__(256, 1)
void gemm_f16(const __half* __restrict__ A, const __half* __restrict__ B,
              void* __restrict__ Cv, int M, int N, int K) {
    extern __shared__ char smc[];
    const uint32_t sb = smem_u32(smc);
    const int tid = threadIdx.x;
    const int bm = blockIdx.y * GBM, bn = blockIdx.x * GBN;
    const int wid = tid >> 5, lane = tid & 31;
    const int wm = wid & 1, wn = wid >> 1;
    const int g = lane >> 2, t = lane & 3;
    const __half* Ag = A + (size_t)bm * K;
    const __half* Bg = B + (size_t)bn * K;

    // ldmatrix per-lane row/col offsets
    const int lrow = (lane & 7) + 8 * ((lane >> 3) & 1);
    const uint32_t lcol = (lane & 16) ? 16 : 0;

    float acc[4][8][4];
#pragma unroll
    for (int i = 0; i < 4; i++)
#pragma unroll
        for (int j = 0; j < 8; j++)
#pragma unroll
            for (int r = 0; r < 4; r++) acc[i][j][r] = 0.f;

    gemm_issue(sb, 0, Ag, Bg, K, 0, tid); CP_COMMIT();
    gemm_issue(sb, 1, Ag, Bg, K, GBK, tid); CP_COMMIT();
    gemm_issue(sb, 2, Ag, Bg, K, 2 * GBK, tid); CP_COMMIT();

    const int NIT = K / GBK;
    for (int it = 0; it < NIT; it++) {
        CP_WAIT2();           // stage `it` landed
        __syncthreads();

        if (it + 3 < NIT)
            gemm_issue(sb, (it + 3) & 3, Ag, Bg, K, (it + 3) * GBK, tid);
        CP_COMMIT();

        const uint32_t stg = sb + (it & 3) * (G_STAGE_H * 2);
        const uint32_t a_base = stg + (wm * 64 + lrow) * 80 + lcol;
        const uint32_t b_base = stg + GBM * 80 + (wn * 64 + lrow) * 80 + lcol;

#pragma unroll
        for (int ks = 0; ks < 2; ks++) {
            unsigned a[4][4], b[8][2];
#pragma unroll
            for (int im = 0; im < 4; im++)
                ldsm4(a[im], a_base + im * 16 * 80 + ks * 32);
#pragma unroll
            for (int jp = 0; jp < 4; jp++) {
                unsigned r[4];
                ldsm4(r, b_base + jp * 16 * 80 + ks * 32);
                b[2 * jp][0] = r[0]; b[2 * jp][1] = r[2];
                b[2 * jp + 1][0] = r[1]; b[2 * jp + 1][1] = r[3];
            }
#pragma unroll
            for (int im = 0; im < 4; im++)
#pragma unroll
                for (int jn = 0; jn < 8; jn++)
                    mma_f16(acc[im][jn], a[im], b[jn]);
        }
    }

#pragma unroll
    for (int im = 0; im < 4; im++) {
        const int r0 = bm + wm * 64 + im * 16 + g;
#pragma unroll
        for (int jn = 0; jn < 8; jn++) {
            const int c0 = bn + wn * 64 + jn * 8 + 2 * t;
            if (HALF_OUT) {
                __half* C = (__half*)Cv;
                *(__half2*)&C[(size_t)r0 * N + c0] =
                    __floats2half2_rn(acc[im][jn][0], acc[im][jn][1]);
                *(__half2*)&C[(size_t)(r0 + 8) * N + c0] =
                    __floats2half2_rn(acc[im][jn][2], acc[im][jn][3]);
            } else {
                float* C = (float*)Cv;
                *(float2*)&C[(size_t)r0 * N + c0] =
                    make_float2(acc[im][jn][0], acc[im][jn][1]);
                *(float2*)&C[(size_t)(r0 + 8) * N + c0] =
                    make_float2(acc[im][jn][2], acc[im][jn][3]);
            }
        }
    }
}

// ---------------------------------------------------------------------------
// Flash attention, fp16 m16n8k16. 256 thr (8 warps), 128 q rows/block, warp w
// owns q rows [16w,16w+16); KV tile 64, double-buffered, one block sync/tile.
// Q fragments hoisted into registers (loop-invariant). K fragments via
// ldmatrix. P never touches smem: S accumulators repack directly into PV
// A-fragments. V transposed+pair-interleaved at store (as round 7).
// Row stride 36 half2 words (144B = 16x9) -> ldmatrix & scalar CF.
// ---------------------------------------------------------------------------
#define FQ 128
#define FK 64
#define FS2 36                           // half2 words per row
#define FQS_OFF 0                        // Qs: 128*36
#define FKS_OFF (FQ * FS2)               // Ks: 2 stages x 64*36
#define FVT_OFF (FKS_OFF + 2 * FK * FS2) // Vt: 2 stages x 64*36
#define FL_WORDS (FVT_OFF + 2 * FK * FS2)
#define FL_SMEM (FL_WORDS * 4)           // 55296 B

__global__ __launch_bounds__(256, 2)
void flash_f16(const __half* __restrict__ qkv, __half* __restrict__ attn) {
    extern __shared__ unsigned sm[];
    const uint32_t sq = smem_u32(sm);

    const int qb = blockIdx.x * FQ;
    const int h = blockIdx.y, b = blockIdx.z;
    const int tid = threadIdx.x;
    const int wid = tid >> 5, lane = tid & 31;
    const int g = lane >> 2, t = lane & 3;
    const int wq = wid * 16;
    const int lrow = (lane & 7) + 8 * ((lane >> 3) & 1);
    const uint32_t lcol = (lane & 16) ? 16 : 0;

    const size_t rs = QKV_COLS;
    const __half* qg = qkv + (size_t)(b * SEQ + qb) * rs + h * HD;
    const __half* kg = qkv + (size_t)(b * SEQ) * rs + HID + h * HD;
    const __half* vg = qkv + (size_t)(b * SEQ) * rs + 2 * HID + h * HD;

    // Stage Q tile: 128 rows x 64 halfs = 1024 x 16B chunks, 4/thread
#pragma unroll
    for (int u = 0; u < 4; u++) {
        const int c = tid * 4 + u;
        const int row = c >> 3, seg = c & 7;
        uint4 v = *(const uint4*)(qg + (size_t)row * rs + seg * 8);
        *(uint4*)&sm[FQS_OFF + row * FS2 + seg * 4] = v;
    }
    __syncthreads();

    // Hoist Q fragments (invariant over KV tiles): 16 regs
    unsigned qa[4][4];
    {
        const uint32_t qbase = sq + (wq + lrow) * (FS2 * 4) + lcol;
#pragma unroll
        for (int ks = 0; ks < 4; ks++) ldsm4(qa[ks], qbase + ks * 32);
    }

    // Loader geometry
    const int kc0 = tid * 2;
    const int krow0 = kc0 >> 3, kseg0 = kc0 & 7;
    const int krow1 = (kc0 + 1) >> 3, kseg1 = (kc0 + 1) & 7;
    const int kv2 = tid & 31;          // pair of kv rows (2kv2, 2kv2+1)
    const int dseg = tid >> 5;         // 8 halfs of d per thread

    float o[8][4];
    float m0 = -1e30f, m1 = -1e30f, l0 = 0.f, l1 = 0.f;
#pragma unroll
    for (int j = 0; j < 8; j++)
#pragma unroll
        for (int r = 0; r < 4; r++) o[j][r] = 0.f;

    // Prologue: prefetch KV tile 0
    uint4 pk0 = *(const uint4*)(kg + (size_t)krow0 * rs + kseg0 * 8);
    uint4 pk1 = *(const uint4*)(kg + (size_t)krow1 * rs + kseg1 * 8);
    uint4 pv0 = *(const uint4*)(vg + (size_t)(2 * kv2) * rs + dseg * 8);
    uint4 pv1 = *(const uint4*)(vg + (size_t)(2 * kv2 + 1) * rs + dseg * 8);

    const int ntiles = SEQ / FK;
    for (int it = 0; it < ntiles; it++) {
        const int kso = FKS_OFF + (it & 1) * (FK * FS2);
        const int vto = FVT_OFF + (it & 1) * (FK * FS2);
        unsigned* Vt = sm + vto;

        // STS K (linear) + Vt (transpose + pair-interleave)
        *(uint4*)&sm[kso + krow0 * FS2 + kseg0 * 4] = pk0;
        *(uint4*)&sm[kso + krow1 * FS2 + kseg1 * 4] = pk1;
        {
            const __half* ev = (const __half*)&pv0;
            const __half* od = (const __half*)&pv1;
#pragma unroll
            for (int j = 0; j < 8; j++)
                Vt[(dseg * 8 + j) * FS2 + kv2] = packh2(__half2float(ev[j]),
                                                        __half2float(od[j]));
        }

        if (it + 1 < ntiles) {
            const size_t ro = (size_t)(it + 1) * FK;
            pk0 = *(const uint4*)(kg + (ro + krow0) * rs + kseg0 * 8);
            pk1 = *(const uint4*)(kg + (ro + krow1) * rs + kseg1 * 8);
            pv0 = *(const uint4*)(vg + (ro + 2 * kv2) * rs + dseg * 8);
            pv1 = *(const uint4*)(vg + (ro + 2 * kv2 + 1) * rs + dseg * 8);
        }
        __syncthreads();

        // S = Q @ K^T (K fragments via ldmatrix)
        float s[8][4];
#pragma unroll
        for (int j = 0; j < 8; j++)
#pragma unroll
            for (int r = 0; r < 4; r++) s[j][r] = 0.f;
        const uint32_t kbase = sq + kso * 4 + lrow * (FS2 * 4) + lcol;
#pragma unroll
        for (int ks = 0; ks < 4; ks++) {
            unsigned bb[8][2];
#pragma unroll
            for (int jp = 0; jp < 4; jp++) {
                unsigned r[4];
                ldsm4(r, kbase + jp * 16 * (FS2 * 4) + ks * 32);
                bb[2 * jp][0] = r[0]; bb[2 * jp][1] = r[2];
                bb[2 * jp + 1][0] = r[1]; bb[2 * jp + 1][1] = r[3];
            }
#pragma unroll
            for (int jn = 0; jn < 8; jn++) mma_f16(s[jn], qa[ks], bb[jn]);
        }

        // Online softmax (raw scores; 1/8 scale folded into exp args)
        float rm0 = -1e30f, rm1 = -1e30f;
#pragma unroll
        for (int j = 0; j < 8; j++) {
            rm0 = fmaxf(rm0, fmaxf(s[j][0], s[j][1]));
            rm1 = fmaxf(rm1, fmaxf(s[j][2], s[j][3]));
        }
        rm0 = fmaxf(rm0, __shfl_xor_sync(0xffffffffu, rm0, 1));
        rm0 = fmaxf(rm0, __shfl_xor_sync(0xffffffffu, rm0, 2));
        rm1 = fmaxf(rm1, __shfl_xor_sync(0xffffffffu, rm1, 1));
        rm1 = fmaxf(rm1, __shfl_xor_sync(0xffffffffu, rm1, 2));
        const float mn0 = fmaxf(m0, rm0), mn1 = fmaxf(m1, rm1);
        const float cr0 = __expf((m0 - mn0) * 0.125f);
        const float cr1 = __expf((m1 - mn1) * 0.125f);
        m0 = mn0; m1 = mn1;
        float sum0 = 0.f, sum1 = 0.f;
#pragma unroll
        for (int j = 0; j < 8; j++) {
            s[j][0] = __expf((s[j][0] - mn0) * 0.125f);
            s[j][1] = __expf((s[j][1] - mn0) * 0.125f);
            s[j][2] = __expf((s[j][2] - mn1) * 0.125f);
            s[j][3] = __expf((s[j][3] - mn1) * 0.125f);
            sum0 += s[j][0] + s[j][1];
            sum1 += s[j][2] + s[j][3];
        }
        sum0 += __shfl_xor_sync(0xffffffffu, sum0, 1);
        sum0 += __shfl_xor_sync(0xffffffffu, sum0, 2);
        sum1 += __shfl_xor_sync(0xffffffffu, sum1, 1);
        sum1 += __shfl_xor_sync(0xffffffffu, sum1, 2);
        l0 = l0 * cr0 + sum0;
        l1 = l1 * cr1 + sum1;
#pragma unroll
        for (int j = 0; j < 8; j++) {
            o[j][0] *= cr0; o[j][1] *= cr0;
            o[j][2] *= cr1; o[j][3] *= cr1;
        }

        // O += P @ V : P repacked in registers as PV A-fragments.
        // a0={P[g][16ks+2t],+1}=s[2ks][0..1], a1=s[2ks][2..3] (rows g+8),
        // a2=s[2ks+1][0..1] (k+8), a3=s[2ks+1][2..3].
#pragma unroll
        for (int ks = 0; ks < 4; ks++) {
            unsigned pa[4];
            pa[0] = packh2(s[2 * ks][0], s[2 * ks][1]);
            pa[1] = packh2(s[2 * ks][2], s[2 * ks][3]);
            pa[2] = packh2(s[2 * ks + 1][0], s[2 * ks + 1][1]);
            pa[3] = packh2(s[2 * ks + 1][2], s[2 * ks + 1][3]);
#pragma unroll
            for (int jn = 0; jn < 8; jn++) {
                unsigned bb[2];
                bb[0] = Vt[(jn * 8 + g) * FS2 + ks * 8 + t];
                bb[1] = Vt[(jn * 8 + g) * FS2 + ks * 8 + t + 4];
                mma_f16(o[jn], pa, bb);
            }
        }
    }

    const float inv0 = 1.f / l0, inv1 = 1.f / l1;
    __half2* out0 = (__half2*)attn + (size_t)(b * SEQ + qb + wq + g) * (HID / 2)
                    + h * (HD / 2);
    __half2* out1 = out0 + (size_t)8 * (HID / 2);
#pragma unroll
    for (int jn = 0; jn < 8; jn++) {
        out0[jn * 4 + t] = __floats2half2_rn(o[jn][0] * inv0, o[jn][1] * inv0);
        out1[jn * 4 + t] = __floats2half2_rn(o[jn][2] * inv1, o[jn][3] * inv1);
    }
}

// ---------------------------------------------------------------------------
extern "C" void kernel_launch(void* const* d_in, const int* in_sizes, int n_in,
                              void* d_out, int out_size) {
    const float* hidden = (const float*)d_in[0];   // [2,2048,1024]
    const float* w_qkv  = (const float*)d_in[1];   // [3072,1024]
    const float* w_o    = (const float*)d_in[2];   // [1024,1024]
    float* out = (float*)d_out;                    // [2,2048,1024]

    __half *hid_h, *wqkv_h, *wo_h, *qkv_h, *attn_h;
    cudaGetSymbolAddress((void**)&hid_h, g_hidden_h);
    cudaGetSymbolAddress((void**)&wqkv_h, g_wqkv_h);
    cudaGetSymbolAddress((void**)&wo_h, g_wo_h);
    cudaGetSymbolAddress((void**)&qkv_h, g_qkv);
    cudaGetSymbolAddress((void**)&attn_h, g_attn);

    static bool attr_set = false;
    if (!attr_set) {
        cudaFuncSetAttribute(gemm_f16<true>,
                             cudaFuncAttributeMaxDynamicSharedMemorySize,
                             GEMM_SMEM);
        cudaFuncSetAttribute(gemm_f16<false>,
                             cudaFuncAttributeMaxDynamicSharedMemorySize,
                             GEMM_SMEM);
        cudaFuncSetAttribute(flash_f16,
                             cudaFuncAttributeMaxDynamicSharedMemorySize,
                             FL_SMEM);
        attr_set = true;
    }

    // 0) fp32 -> fp16 pre-convert of the three inputs
    cvt_h<<<(ROWS * HID) / 1024, 256>>>(hidden, hid_h);
    cvt_h<<<(QKV_COLS * HID) / 1024, 256>>>(w_qkv, wqkv_h);
    cvt_h<<<(HID * HID) / 1024, 256>>>(w_o, wo_h);

    // 1) QKV projection -> g_qkv (half): [4096,1024] @ [3072,1024]^T
    {
        dim3 grid(QKV_COLS / GBN, ROWS / GBM);   // (12, 32)
        gemm_f16<true><<<grid, 256, GEMM_SMEM>>>(hid_h, wqkv_h, qkv_h,
                                                 ROWS, QKV_COLS, HID);
    }

    // 2) Flash attention -> g_attn (half), [B,S,H] layout
    {
        dim3 grid(SEQ / FQ, NH, BATCH);          // (16, 16, 2)
        flash_f16<<<grid, 256, FL_SMEM>>>(qkv_h, attn_h);
    }

    // 3) Output projection -> fp32 out: [4096,1024] @ [1024,1024]^T
    {
        dim3 grid(HID / GBN, ROWS / GBM);        // (4, 32)
        gemm_f16<false><<<grid, 256, GEMM_SMEM>>>(attn_h, wo_h, out,
                                                  ROWS, HID, HID);
    }
}

// round 11
// speedup vs baseline: 5.6288x; 1.1148x over previous
#include <cuda_runtime.h>
#include <cuda_fp16.h>
#include <math.h>
#include <cstdint>

// Problem constants: B=2, S=2048, H=1024, nh=16, hd=64
#define BATCH 2
#define SEQ   2048
#define HID   1024
#define NH    16
#define HD    64
#define ROWS  (BATCH * SEQ)        // 4096
#define QKV_COLS (3 * HID)         // 3072

// fp16 scratch (no allocations allowed)
__device__ __half g_hidden_h[ROWS * HID];
__device__ __half g_wqkv_h[QKV_COLS * HID];
__device__ __half g_wo_h[HID * HID];
__device__ __half g_qkv[ROWS * QKV_COLS];
__device__ __half g_attn[ROWS * HID];

// ---------------------------------------------------------------------------
// Helpers
// ---------------------------------------------------------------------------
__device__ __forceinline__ uint32_t smem_u32(const void* p) {
    uint32_t a;
    asm("{ .reg .u64 t; cvta.to.shared.u64 t, %1; cvt.u32.u64 %0, t; }"
        : "=r"(a) : "l"(p));
    return a;
}

__device__ __forceinline__ void mma_f16(float c[4], const unsigned a[4],
                                        const unsigned b[2]) {
    asm volatile(
        "mma.sync.aligned.m16n8k16.row.col.f32.f16.f16.f32 "
        "{%0,%1,%2,%3}, {%4,%5,%6,%7}, {%8,%9}, {%0,%1,%2,%3};\n"
        : "+f"(c[0]), "+f"(c[1]), "+f"(c[2]), "+f"(c[3])
        : "r"(a[0]), "r"(a[1]), "r"(a[2]), "r"(a[3]), "r"(b[0]), "r"(b[1]));
}

__device__ __forceinline__ void ldsm4(unsigned r[4], uint32_t addr) {
    asm volatile(
        "ldmatrix.sync.aligned.m8n8.x4.shared.b16 {%0,%1,%2,%3}, [%4];"
        : "=r"(r[0]), "=r"(r[1]), "=r"(r[2]), "=r"(r[3]) : "r"(addr));
}

__device__ __forceinline__ void cp_async16(uint32_t dst, const void* src) {
    asm volatile("cp.async.cg.shared.global [%0], [%1], 16;\n"
                 :: "r"(dst), "l"(src));
}
#define CP_COMMIT() asm volatile("cp.async.commit_group;\n" ::: "memory")
#define CP_WAIT2()  asm volatile("cp.async.wait_group 2;\n" ::: "memory")

__device__ __forceinline__ unsigned packh2(float x, float y) {
    __half2 h = __floats2half2_rn(x, y);
    return *(unsigned*)&h;
}

// ---------------------------------------------------------------------------
// fp32 -> fp16 convert (pre-pass)
// ---------------------------------------------------------------------------
__global__ void cvt_h(const float* __restrict__ in, __half* __restrict__ out) {
    int i = (blockIdx.x * blockDim.x + threadIdx.x) * 4;
    float4 v = *(const float4*)(in + i);
    *(__half2*)(out + i)     = __floats2half2_rn(v.x, v.y);
    *(__half2*)(out + i + 2) = __floats2half2_rn(v.z, v.w);
}

// ---------------------------------------------------------------------------
// fp16 GEMM: C[M,N] = A[M,K] @ B[N,K]^T (both K-contiguous, half).
// Block 128x256x32(halfs), 512 thr = 16 warps (4m x 4n), warp tile 32x64.
// 4 warps per SMSP so LDSM/sync stalls of one warp overlap with HMMA streams
// of three others. 4-stage cp.async pipeline. smem row = 32 halfs + 8 pad
// (80B = 16x5): ldmatrix rows hit 8 distinct 16B banks -> conflict-free.
// ---------------------------------------------------------------------------
#define GBM 128
#define GBN 256
#define GBK 32
#define GROW 40                              // halfs per padded row
#define G_STAGE_H ((GBM + GBN) * GROW)       // 15360 halfs / stage
#define G_NST 4
#define GEMM_SMEM (G_NST * G_STAGE_H * 2)    // 122880 B

__device__ __forceinline__ void gemm_issue(uint32_t sbase, int stage,
                                           const __half* Ag, const __half* Bg,
                                           int K, int kt, int tid) {
    const uint32_t st = sbase + stage * (G_STAGE_H * 2);
    // A: 512 chunks of 16B, 1/thread
    {
        const int row = tid >> 2, seg = tid & 3;
        cp_async16(st + row * 80 + seg * 16,
                   Ag + (size_t)row * K + kt + seg * 8);
    }
    // B: 1024 chunks of 16B, 2/thread
    {
        const uint32_t bs = st + GBM * 80;
        const int row = tid >> 1, sg0 = (tid & 1) * 2;
        cp_async16(bs + row * 80 + sg0 * 16,
                   Bg + (size_t)row * K + kt + sg0 * 8);
        cp_async16(bs + row * 80 + (sg0 + 1) * 16,
                   Bg + (size_t)row * K + kt + (sg0 + 1) * 8);
    }
}

template <bool HALF_OUT>
__global__ __launch_bounds__(512, 1)
void gemm_f16(const __half* __restrict__ A, const __half* __restrict__ B,
              void* __restrict__ Cv, int M, int N, int K) {
    extern __shared__ char smc[];
    const uint32_t sb = smem_u32(smc);
    const int tid = threadIdx.x;
    const int bm = blockIdx.y * GBM, bn = blockIdx.x * GBN;
    const int wid = tid >> 5, lane = tid & 31;
    const int wm = wid & 3, wn = wid >> 2;     // 4m x 4n warps
    const int g = lane >> 2, t = lane & 3;
    const __half* Ag = A + (size_t)bm * K;
    const __half* Bg = B + (size_t)bn * K;

    // ldmatrix per-lane row/col offsets
    const int lrow = (lane & 7) + 8 * ((lane >> 3) & 1);
    const uint32_t lcol = (lane & 16) ? 16 : 0;

    float acc[2][8][4];
#pragma unroll
    for (int i = 0; i < 2; i++)
#pragma unroll
        for (int j = 0; j < 8; j++)
#pragma unroll
            for (int r = 0; r < 4; r++) acc[i][j][r] = 0.f;

    gemm_issue(sb, 0, Ag, Bg, K, 0, tid); CP_COMMIT();
    gemm_issue(sb, 1, Ag, Bg, K, GBK, tid); CP_COMMIT();
    gemm_issue(sb, 2, Ag, Bg, K, 2 * GBK, tid); CP_COMMIT();

    const int NIT = K / GBK;
    for (int it = 0; it < NIT; it++) {
        CP_WAIT2();           // stage `it` landed
        __syncthreads();

        if (it + 3 < NIT)
            gemm_issue(sb, (it + 3) & 3, Ag, Bg, K, (it + 3) * GBK, tid);
        CP_COMMIT();

        const uint32_t stg = sb + (it & 3) * (G_STAGE_H * 2);
        const uint32_t a_base = stg + (wm * 32 + lrow) * 80 + lcol;
        const uint32_t b_base = stg + GBM * 80 + (wn * 64 + lrow) * 80 + lcol;

#pragma unroll
        for (int ks = 0; ks < 2; ks++) {
            unsigned a[2][4], b[8][2];
#pragma unroll
            for (int im = 0; im < 2; im++)
                ldsm4(a[im], a_base + im * 16 * 80 + ks * 32);
#pragma unroll
            for (int jp = 0; jp < 4; jp++) {
                unsigned r[4];
                ldsm4(r, b_base + jp * 16 * 80 + ks * 32);
                b[2 * jp][0] = r[0]; b[2 * jp][1] = r[2];
                b[2 * jp + 1][0] = r[1]; b[2 * jp + 1][1] = r[3];
            }
#pragma unroll
            for (int im = 0; im < 2; im++)
#pragma unroll
                for (int jn = 0; jn < 8; jn++)
                    mma_f16(acc[im][jn], a[im], b[jn]);
        }
    }

#pragma unroll
    for (int im = 0; im < 2; im++) {
        const int r0 = bm + wm * 32 + im * 16 + g;
#pragma unroll
        for (int jn = 0; jn < 8; jn++) {
            const int c0 = bn + wn * 64 + jn * 8 + 2 * t;
            if (HALF_OUT) {
                __half* C = (__half*)Cv;
                *(__half2*)&C[(size_t)r0 * N + c0] =
                    __floats2half2_rn(acc[im][jn][0], acc[im][jn][1]);
                *(__half2*)&C[(size_t)(r0 + 8) * N + c0] =
                    __floats2half2_rn(acc[im][jn][2], acc[im][jn][3]);
            } else {
                float* C = (float*)Cv;
                *(float2*)&C[(size_t)r0 * N + c0] =
                    make_float2(acc[im][jn][0], acc[im][jn][1]);
                *(float2*)&C[(size_t)(r0 + 8) * N + c0] =
                    make_float2(acc[im][jn][2], acc[im][jn][3]);
            }
        }
    }
}

// ---------------------------------------------------------------------------
// Flash attention, fp16 m16n8k16 (unchanged from round 10 — already 4
// warps/SMSP via 2 CTAs/SM). 256 thr, 128 q rows/block, KV tile 64 double-
// buffered, Q fragments hoisted, K via ldmatrix, P register-resident.
// ---------------------------------------------------------------------------
#define FQ 128
#define FK 64
#define FS2 36                           // half2 words per row
#define FQS_OFF 0                        // Qs: 128*36
#define FKS_OFF (FQ * FS2)               // Ks: 2 stages x 64*36
#define FVT_OFF (FKS_OFF + 2 * FK * FS2) // Vt: 2 stages x 64*36
#define FL_WORDS (FVT_OFF + 2 * FK * FS2)
#define FL_SMEM (FL_WORDS * 4)           // 55296 B

__global__ __launch_bounds__(256, 2)
void flash_f16(const __half* __restrict__ qkv, __half* __restrict__ attn) {
    extern __shared__ unsigned sm[];
    const uint32_t sq = smem_u32(sm);

    const int qb = blockIdx.x * FQ;
    const int h = blockIdx.y, b = blockIdx.z;
    const int tid = threadIdx.x;
    const int wid = tid >> 5, lane = tid & 31;
    const int g = lane >> 2, t = lane & 3;
    const int wq = wid * 16;
    const int lrow = (lane & 7) + 8 * ((lane >> 3) & 1);
    const uint32_t lcol = (lane & 16) ? 16 : 0;

    const size_t rs = QKV_COLS;
    const __half* qg = qkv + (size_t)(b * SEQ + qb) * rs + h * HD;
    const __half* kg = qkv + (size_t)(b * SEQ) * rs + HID + h * HD;
    const __half* vg = qkv + (size_t)(b * SEQ) * rs + 2 * HID + h * HD;

    // Stage Q tile: 128 rows x 64 halfs = 1024 x 16B chunks, 4/thread
#pragma unroll
    for (int u = 0; u < 4; u++) {
        const int c = tid * 4 + u;
        const int row = c >> 3, seg = c & 7;
        uint4 v = *(const uint4*)(qg + (size_t)row * rs + seg * 8);
        *(uint4*)&sm[FQS_OFF + row * FS2 + seg * 4] = v;
    }
    __syncthreads();

    // Hoist Q fragments (invariant over KV tiles)
    unsigned qa[4][4];
    {
        const uint32_t qbase = sq + (wq + lrow) * (FS2 * 4) + lcol;
#pragma unroll
        for (int ks = 0; ks < 4; ks++) ldsm4(qa[ks], qbase + ks * 32);
    }

    // Loader geometry
    const int kc0 = tid * 2;
    const int krow0 = kc0 >> 3, kseg0 = kc0 & 7;
    const int krow1 = (kc0 + 1) >> 3, kseg1 = (kc0 + 1) & 7;
    const int kv2 = tid & 31;          // pair of kv rows (2kv2, 2kv2+1)
    const int dseg = tid >> 5;         // 8 halfs of d per thread

    float o[8][4];
    float m0 = -1e30f, m1 = -1e30f, l0 = 0.f, l1 = 0.f;
#pragma unroll
    for (int j = 0; j < 8; j++)
#pragma unroll
        for (int r = 0; r < 4; r++) o[j][r] = 0.f;

    // Prologue: prefetch KV tile 0
    uint4 pk0 = *(const uint4*)(kg + (size_t)krow0 * rs + kseg0 * 8);
    uint4 pk1 = *(const uint4*)(kg + (size_t)krow1 * rs + kseg1 * 8);
    uint4 pv0 = *(const uint4*)(vg + (size_t)(2 * kv2) * rs + dseg * 8);
    uint4 pv1 = *(const uint4*)(vg + (size_t)(2 * kv2 + 1) * rs + dseg * 8);

    const int ntiles = SEQ / FK;
    for (int it = 0; it < ntiles; it++) {
        const int kso = FKS_OFF + (it & 1) * (FK * FS2);
        const int vto = FVT_OFF + (it & 1) * (FK * FS2);
        unsigned* Vt = sm + vto;

        // STS K (linear) + Vt (transpose + pair-interleave)
        *(uint4*)&sm[kso + krow0 * FS2 + kseg0 * 4] = pk0;
        *(uint4*)&sm[kso + krow1 * FS2 + kseg1 * 4] = pk1;
        {
            const __half* ev = (const __half*)&pv0;
            const __half* od = (const __half*)&pv1;
#pragma unroll
            for (int j = 0; j < 8; j++)
                Vt[(dseg * 8 + j) * FS2 + kv2] = packh2(__half2float(ev[j]),
                                                        __half2float(od[j]));
        }

        if (it + 1 < ntiles) {
            const size_t ro = (size_t)(it + 1) * FK;
            pk0 = *(const uint4*)(kg + (ro + krow0) * rs + kseg0 * 8);
            pk1 = *(const uint4*)(kg + (ro + krow1) * rs + kseg1 * 8);
            pv0 = *(const uint4*)(vg + (ro + 2 * kv2) * rs + dseg * 8);
            pv1 = *(const uint4*)(vg + (ro + 2 * kv2 + 1) * rs + dseg * 8);
        }
        __syncthreads();

        // S = Q @ K^T (K fragments via ldmatrix)
        float s[8][4];
#pragma unroll
        for (int j = 0; j < 8; j++)
#pragma unroll
            for (int r = 0; r < 4; r++) s[j][r] = 0.f;
        const uint32_t kbase = sq + kso * 4 + lrow * (FS2 * 4) + lcol;
#pragma unroll
        for (int ks = 0; ks < 4; ks++) {
            unsigned bb[8][2];
#pragma unroll
            for (int jp = 0; jp < 4; jp++) {
                unsigned r[4];
                ldsm4(r, kbase + jp * 16 * (FS2 * 4) + ks * 32);
                bb[2 * jp][0] = r[0]; bb[2 * jp][1] = r[2];
                bb[2 * jp + 1][0] = r[1]; bb[2 * jp + 1][1] = r[3];
            }
#pragma unroll
            for (int jn = 0; jn < 8; jn++) mma_f16(s[jn], qa[ks], bb[jn]);
        }

        // Online softmax (raw scores; 1/8 scale folded into exp args)
        float rm0 = -1e30f, rm1 = -1e30f;
#pragma unroll
        for (int j = 0; j < 8; j++) {
            rm0 = fmaxf(rm0, fmaxf(s[j][0], s[j][1]));
            rm1 = fmaxf(rm1, fmaxf(s[j][2], s[j][3]));
        }
        rm0 = fmaxf(rm0, __shfl_xor_sync(0xffffffffu, rm0, 1));
        rm0 = fmaxf(rm0, __shfl_xor_sync(0xffffffffu, rm0, 2));
        rm1 = fmaxf(rm1, __shfl_xor_sync(0xffffffffu, rm1, 1));
        rm1 = fmaxf(rm1, __shfl_xor_sync(0xffffffffu, rm1, 2));
        const float mn0 = fmaxf(m0, rm0), mn1 = fmaxf(m1, rm1);
        const float cr0 = __expf((m0 - mn0) * 0.125f);
        const float cr1 = __expf((m1 - mn1) * 0.125f);
        m0 = mn0; m1 = mn1;
        float sum0 = 0.f, sum1 = 0.f;
#pragma unroll
        for (int j = 0; j < 8; j++) {
            s[j][0] = __expf((s[j][0] - mn0) * 0.125f);
            s[j][1] = __expf((s[j][1] - mn0) * 0.125f);
            s[j][2] = __expf((s[j][2] - mn1) * 0.125f);
            s[j][3] = __expf((s[j][3] - mn1) * 0.125f);
            sum0 += s[j][0] + s[j][1];
            sum1 += s[j][2] + s[j][3];
        }
        sum0 += __shfl_xor_sync(0xffffffffu, sum0, 1);
        sum0 += __shfl_xor_sync(0xffffffffu, sum0, 2);
        sum1 += __shfl_xor_sync(0xffffffffu, sum1, 1);
        sum1 += __shfl_xor_sync(0xffffffffu, sum1, 2);
        l0 = l0 * cr0 + sum0;
        l1 = l1 * cr1 + sum1;
#pragma unroll
        for (int j = 0; j < 8; j++) {
            o[j][0] *= cr0; o[j][1] *= cr0;
            o[j][2] *= cr1; o[j][3] *= cr1;
        }

        // O += P @ V : P repacked in registers as PV A-fragments
#pragma unroll
        for (int ks = 0; ks < 4; ks++) {
            unsigned pa[4];
            pa[0] = packh2(s[2 * ks][0], s[2 * ks][1]);
            pa[1] = packh2(s[2 * ks][2], s[2 * ks][3]);
            pa[2] = packh2(s[2 * ks + 1][0], s[2 * ks + 1][1]);
            pa[3] = packh2(s[2 * ks + 1][2], s[2 * ks + 1][3]);
#pragma unroll
            for (int jn = 0; jn < 8; jn++) {
                unsigned bb[2];
                bb[0] = Vt[(jn * 8 + g) * FS2 + ks * 8 + t];
                bb[1] = Vt[(jn * 8 + g) * FS2 + ks * 8 + t + 4];
                mma_f16(o[jn], pa, bb);
            }
        }
    }

    const float inv0 = 1.f / l0, inv1 = 1.f / l1;
    __half2* out0 = (__half2*)attn + (size_t)(b * SEQ + qb + wq + g) * (HID / 2)
                    + h * (HD / 2);
    __half2* out1 = out0 + (size_t)8 * (HID / 2);
#pragma unroll
    for (int jn = 0; jn < 8; jn++) {
        out0[jn * 4 + t] = __floats2half2_rn(o[jn][0] * inv0, o[jn][1] * inv0);
        out1[jn * 4 + t] = __floats2half2_rn(o[jn][2] * inv1, o[jn][3] * inv1);
    }
}

// ---------------------------------------------------------------------------
extern "C" void kernel_launch(void* const* d_in, const int* in_sizes, int n_in,
                              void* d_out, int out_size) {
    const float* hidden = (const float*)d_in[0];   // [2,2048,1024]
    const float* w_qkv  = (const float*)d_in[1];   // [3072,1024]
    const float* w_o    = (const float*)d_in[2];   // [1024,1024]
    float* out = (float*)d_out;                    // [2,2048,1024]

    __half *hid_h, *wqkv_h, *wo_h, *qkv_h, *attn_h;
    cudaGetSymbolAddress((void**)&hid_h, g_hidden_h);
    cudaGetSymbolAddress((void**)&wqkv_h, g_wqkv_h);
    cudaGetSymbolAddress((void**)&wo_h, g_wo_h);
    cudaGetSymbolAddress((void**)&qkv_h, g_qkv);
    cudaGetSymbolAddress((void**)&attn_h, g_attn);

    static bool attr_set = false;
    if (!attr_set) {
        cudaFuncSetAttribute(gemm_f16<true>,
                             cudaFuncAttributeMaxDynamicSharedMemorySize,
                             GEMM_SMEM);
        cudaFuncSetAttribute(gemm_f16<false>,
                             cudaFuncAttributeMaxDynamicSharedMemorySize,
                             GEMM_SMEM);
        cudaFuncSetAttribute(flash_f16,
                             cudaFuncAttributeMaxDynamicSharedMemorySize,
                             FL_SMEM);
        attr_set = true;
    }

    // 0) fp32 -> fp16 pre-convert of the three inputs
    cvt_h<<<(ROWS * HID) / 1024, 256>>>(hidden, hid_h);
    cvt_h<<<(QKV_COLS * HID) / 1024, 256>>>(w_qkv, wqkv_h);
    cvt_h<<<(HID * HID) / 1024, 256>>>(w_o, wo_h);

    // 1) QKV projection -> g_qkv (half): [4096,1024] @ [3072,1024]^T
    {
        dim3 grid(QKV_COLS / GBN, ROWS / GBM);   // (12, 32)
        gemm_f16<true><<<grid, 512, GEMM_SMEM>>>(hid_h, wqkv_h, qkv_h,
                                                 ROWS, QKV_COLS, HID);
    }

    // 2) Flash attention -> g_attn (half), [B,S,H] layout
    {
        dim3 grid(SEQ / FQ, NH, BATCH);          // (16, 16, 2)
        flash_f16<<<grid, 256, FL_SMEM>>>(qkv_h, attn_h);
    }

    // 3) Output projection -> fp32 out: [4096,1024] @ [1024,1024]^T
    {
        dim3 grid(HID / GBN, ROWS / GBM);        // (4, 32)
        gemm_f16<false><<<grid, 512, GEMM_SMEM>>>(attn_h, wo_h, out,
                                                  ROWS, HID, HID);
    }
}

// round 13
// speedup vs baseline: 6.2184x; 1.1048x over previous
#include <cuda_runtime.h>
#include <cuda_fp16.h>
#include <math.h>
#include <cstdint>

// Problem constants: B=2, S=2048, H=1024, nh=16, hd=64
#define BATCH 2
#define SEQ   2048
#define HID   1024
#define NH    16
#define HD    64
#define ROWS  (BATCH * SEQ)        // 4096
#define QKV_COLS (3 * HID)         // 3072

// fp16 scratch (no allocations allowed)
__device__ __half g_hidden_h[ROWS * HID];
__device__ __half g_wqkv_h[QKV_COLS * HID];
__device__ __half g_wo_h[HID * HID];
__device__ __half g_qkv[ROWS * QKV_COLS];
__device__ __half g_attn[ROWS * HID];

// ---------------------------------------------------------------------------
// Helpers
// ---------------------------------------------------------------------------
__device__ __forceinline__ uint32_t smem_u32(const void* p) {
    uint32_t a;
    asm("{ .reg .u64 t; cvta.to.shared.u64 t, %1; cvt.u32.u64 %0, t; }"
        : "=r"(a) : "l"(p));
    return a;
}

__device__ __forceinline__ void mma_f16(float c[4], const unsigned a[4],
                                        const unsigned b[2]) {
    asm volatile(
        "mma.sync.aligned.m16n8k16.row.col.f32.f16.f16.f32 "
        "{%0,%1,%2,%3}, {%4,%5,%6,%7}, {%8,%9}, {%0,%1,%2,%3};\n"
        : "+f"(c[0]), "+f"(c[1]), "+f"(c[2]), "+f"(c[3])
        : "r"(a[0]), "r"(a[1]), "r"(a[2]), "r"(a[3]), "r"(b[0]), "r"(b[1]));
}

__device__ __forceinline__ void ldsm4(unsigned r[4], uint32_t addr) {
    asm volatile(
        "ldmatrix.sync.aligned.m8n8.x4.shared.b16 {%0,%1,%2,%3}, [%4];"
        : "=r"(r[0]), "=r"(r[1]), "=r"(r[2]), "=r"(r[3]) : "r"(addr));
}

__device__ __forceinline__ void ldsm4t(unsigned r[4], uint32_t addr) {
    asm volatile(
        "ldmatrix.sync.aligned.m8n8.x4.trans.shared.b16 {%0,%1,%2,%3}, [%4];"
        : "=r"(r[0]), "=r"(r[1]), "=r"(r[2]), "=r"(r[3]) : "r"(addr));
}

__device__ __forceinline__ void cp_async16(uint32_t dst, const void* src) {
    asm volatile("cp.async.cg.shared.global [%0], [%1], 16;\n"
                 :: "r"(dst), "l"(src));
}
#define CP_COMMIT() asm volatile("cp.async.commit_group;\n" ::: "memory")
#define CP_WAIT1()  asm volatile("cp.async.wait_group 1;\n" ::: "memory")
#define CP_WAIT2()  asm volatile("cp.async.wait_group 2;\n" ::: "memory")

__device__ __forceinline__ unsigned packh2(float x, float y) {
    __half2 h = __floats2half2_rn(x, y);
    return *(unsigned*)&h;
}

// ---------------------------------------------------------------------------
// fp32 -> fp16 convert, all three inputs in one launch
// ---------------------------------------------------------------------------
#define NA (ROWS * HID)            // 4194304
#define NB (QKV_COLS * HID)        // 3145728
#define NC (HID * HID)             // 1048576

__global__ void cvt_all(const float* __restrict__ a, const float* __restrict__ b,
                        const float* __restrict__ c, __half* __restrict__ oa,
                        __half* __restrict__ ob, __half* __restrict__ oc) {
    int i = (blockIdx.x * blockDim.x + threadIdx.x) * 4;
    const float* in;
    __half* out;
    int off;
    if (i < NA) { in = a; out = oa; off = i; }
    else if (i < NA + NB) { in = b; out = ob; off = i - NA; }
    else { in = c; out = oc; off = i - NA - NB; }
    float4 v = *(const float4*)(in + off);
    *(__half2*)(out + off)     = __floats2half2_rn(v.x, v.y);
    *(__half2*)(out + off + 2) = __floats2half2_rn(v.z, v.w);
}

// ---------------------------------------------------------------------------
// fp16 GEMM (unchanged from round 11): C[M,N] = A[M,K] @ B[N,K]^T.
// Block 128x256x32, 512 thr = 16 warps (4m x 4n), warp tile 32x64,
// 4-stage cp.async, 80B padded rows (conflict-free ldmatrix).
// ---------------------------------------------------------------------------
#define GBM 128
#define GBN 256
#define GBK 32
#define GROW 40
#define G_STAGE_H ((GBM + GBN) * GROW)
#define G_NST 4
#define GEMM_SMEM (G_NST * G_STAGE_H * 2)    // 122880 B

__device__ __forceinline__ void gemm_issue(uint32_t sbase, int stage,
                                           const __half* Ag, const __half* Bg,
                                           int K, int kt, int tid) {
    const uint32_t st = sbase + stage * (G_STAGE_H * 2);
    {
        const int row = tid >> 2, seg = tid & 3;
        cp_async16(st + row * 80 + seg * 16,
                   Ag + (size_t)row * K + kt + seg * 8);
    }
    {
        const uint32_t bs = st + GBM * 80;
        const int row = tid >> 1, sg0 = (tid & 1) * 2;
        cp_async16(bs + row * 80 + sg0 * 16,
                   Bg + (size_t)row * K + kt + sg0 * 8);
        cp_async16(bs + row * 80 + (sg0 + 1) * 16,
                   Bg + (size_t)row * K + kt + (sg0 + 1) * 8);
    }
}

template <bool HALF_OUT>
__global__ __launch_bounds__(512, 1)
void gemm_f16(const __half* __restrict__ A, const __half* __restrict__ B,
              void* __restrict__ Cv, int M, int N, int K) {
    extern __shared__ char smc[];
    const uint32_t sb = smem_u32(smc);
    const int tid = threadIdx.x;
    const int bm = blockIdx.y * GBM, bn = blockIdx.x * GBN;
    const int wid = tid >> 5, lane = tid & 31;
    const int wm = wid & 3, wn = wid >> 2;
    const int g = lane >> 2, t = lane & 3;
    const __half* Ag = A + (size_t)bm * K;
    const __half* Bg = B + (size_t)bn * K;

    const int lrow = (lane & 7) + 8 * ((lane >> 3) & 1);
    const uint32_t lcol = (lane & 16) ? 16 : 0;

    float acc[2][8][4];
#pragma unroll
    for (int i = 0; i < 2; i++)
#pragma unroll
        for (int j = 0; j < 8; j++)
#pragma unroll
            for (int r = 0; r < 4; r++) acc[i][j][r] = 0.f;

    gemm_issue(sb, 0, Ag, Bg, K, 0, tid); CP_COMMIT();
    gemm_issue(sb, 1, Ag, Bg, K, GBK, tid); CP_COMMIT();
    gemm_issue(sb, 2, Ag, Bg, K, 2 * GBK, tid); CP_COMMIT();

    const int NIT = K / GBK;
    for (int it = 0; it < NIT; it++) {
        CP_WAIT2();
        __syncthreads();

        if (it + 3 < NIT)
            gemm_issue(sb, (it + 3) & 3, Ag, Bg, K, (it + 3) * GBK, tid);
        CP_COMMIT();

        const uint32_t stg = sb + (it & 3) * (G_STAGE_H * 2);
        const uint32_t a_base = stg + (wm * 32 + lrow) * 80 + lcol;
        const uint32_t b_base = stg + GBM * 80 + (wn * 64 + lrow) * 80 + lcol;

#pragma unroll
        for (int ks = 0; ks < 2; ks++) {
            unsigned a[2][4], b[8][2];
#pragma unroll
            for (int im = 0; im < 2; im++)
                ldsm4(a[im], a_base + im * 16 * 80 + ks * 32);
#pragma unroll
            for (int jp = 0; jp < 4; jp++) {
                unsigned r[4];
                ldsm4(r, b_base + jp * 16 * 80 + ks * 32);
                b[2 * jp][0] = r[0]; b[2 * jp][1] = r[2];
                b[2 * jp + 1][0] = r[1]; b[2 * jp + 1][1] = r[3];
            }
#pragma unroll
            for (int im = 0; im < 2; im++)
#pragma unroll
                for (int jn = 0; jn < 8; jn++)
                    mma_f16(acc[im][jn], a[im], b[jn]);
        }
    }

#pragma unroll
    for (int im = 0; im < 2; im++) {
        const int r0 = bm + wm * 32 + im * 16 + g;
#pragma unroll
        for (int jn = 0; jn < 8; jn++) {
            const int c0 = bn + wn * 64 + jn * 8 + 2 * t;
            if (HALF_OUT) {
                __half* C = (__half*)Cv;
                *(__half2*)&C[(size_t)r0 * N + c0] =
                    __floats2half2_rn(acc[im][jn][0], acc[im][jn][1]);
                *(__half2*)&C[(size_t)(r0 + 8) * N + c0] =
                    __floats2half2_rn(acc[im][jn][2], acc[im][jn][3]);
            } else {
                float* C = (float*)Cv;
                *(float2*)&C[(size_t)r0 * N + c0] =
                    make_float2(acc[im][jn][0], acc[im][jn][1]);
                *(float2*)&C[(size_t)(r0 + 8) * N + c0] =
                    make_float2(acc[im][jn][2], acc[im][jn][3]);
            }
        }
    }
}

// ---------------------------------------------------------------------------
// Flash attention, fp16 m16n8k16. 256 thr (8 warps), 128 q rows/block,
// KV tile 64, 3-stage cp.async pipeline (K and V loaded linearly; V
// transposed at fragment-load time via ldmatrix.trans). Q fragments hoisted;
// P register-resident. Row stride 36 half2 (144B) -> conflict-free.
// ---------------------------------------------------------------------------
#define FQ 128
#define FK 64
#define FS2 36                           // half2 words per row
#define FROWB (FS2 * 4)                  // 144 bytes per row
#define FQS_OFF 0                        // Qs: 128*36 words
#define FKS_OFF (FQ * FS2)               // Ks: 3 stages x 64*36
#define FVS_OFF (FKS_OFF + 3 * FK * FS2) // Vs: 3 stages x 64*36
#define FL_WORDS (FVS_OFF + 3 * FK * FS2)
#define FL_SMEM (FL_WORDS * 4)           // 73728 B

__device__ __forceinline__ void flash_issue(uint32_t sbase, int stage,
                                            const __half* kg, const __half* vg,
                                            size_t rs, int kt, int tid) {
    // K tile: 64 rows x 128B = 512 x 16B chunks, 2/thread. Same for V.
    const int row = tid >> 2, sg0 = (tid & 3) * 2;
    const uint32_t kd = sbase + FKS_OFF * 4 + stage * (FK * FROWB);
    const uint32_t vd = sbase + FVS_OFF * 4 + stage * (FK * FROWB);
    const __half* ks = kg + (size_t)(kt + row) * rs + sg0 * 8;
    const __half* vs = vg + (size_t)(kt + row) * rs + sg0 * 8;
    cp_async16(kd + row * FROWB + sg0 * 16, ks);
    cp_async16(kd + row * FROWB + (sg0 + 1) * 16, ks + 8);
    cp_async16(vd + row * FROWB + sg0 * 16, vs);
    cp_async16(vd + row * FROWB + (sg0 + 1) * 16, vs + 8);
}

__global__ __launch_bounds__(256, 2)
void flash_f16(const __half* __restrict__ qkv, __half* __restrict__ attn) {
    extern __shared__ unsigned sm[];
    const uint32_t sq = smem_u32(sm);

    const int qb = blockIdx.x * FQ;
    const int h = blockIdx.y, b = blockIdx.z;
    const int tid = threadIdx.x;
    const int wid = tid >> 5, lane = tid & 31;
    const int g = lane >> 2, t = lane & 3;
    const int wq = wid * 16;
    const int lrow = (lane & 7) + 8 * ((lane >> 3) & 1);
    const uint32_t lcol = (lane & 16) ? 16 : 0;
    const int vrow = lane & 15;                     // ldsm trans row
    const uint32_t vcol = (lane & 16) ? 16 : 0;     // +8 d for hi half-warp

    const size_t rs = QKV_COLS;
    const __half* qg = qkv + (size_t)(b * SEQ + qb) * rs + h * HD;
    const __half* kg = qkv + (size_t)(b * SEQ) * rs + HID + h * HD;
    const __half* vg = qkv + (size_t)(b * SEQ) * rs + 2 * HID + h * HD;

    // Stage Q tile (once): 128 rows x 64 halfs = 1024 x 16B chunks, 4/thread
#pragma unroll
    for (int u = 0; u < 4; u++) {
        const int c = tid * 4 + u;
        const int row = c >> 3, seg = c & 7;
        uint4 v = *(const uint4*)(qg + (size_t)row * rs + seg * 8);
        *(uint4*)&sm[FQS_OFF + row * FS2 + seg * 4] = v;
    }

    // Prologue: start KV tiles 0 and 1
    flash_issue(sq, 0, kg, vg, rs, 0, tid); CP_COMMIT();
    flash_issue(sq, 1, kg, vg, rs, FK, tid); CP_COMMIT();

    __syncthreads();   // Q visible

    // Hoist Q fragments (invariant over KV tiles)
    unsigned qa[4][4];
    {
        const uint32_t qbase = sq + (wq + lrow) * FROWB + lcol;
#pragma unroll
        for (int ks = 0; ks < 4; ks++) ldsm4(qa[ks], qbase + ks * 32);
    }

    float o[8][4];
    float m0 = -1e30f, m1 = -1e30f, l0 = 0.f, l1 = 0.f;
#pragma unroll
    for (int j = 0; j < 8; j++)
#pragma unroll
        for (int r = 0; r < 4; r++) o[j][r] = 0.f;

    const float SC = 0.1803368801111244f;   // 0.125 * log2(e)

    const int ntiles = SEQ / FK;
    for (int it = 0; it < ntiles; it++) {
        CP_WAIT1();          // tile `it` landed (it+1 may be in flight)
        __syncthreads();     // all warps done reading stage (it+2)%3

        if (it + 2 < ntiles)
            flash_issue(sq, (it + 2) % 3, kg, vg, rs, (it + 2) * FK, tid);
        CP_COMMIT();

        const uint32_t kst = sq + FKS_OFF * 4 + (it % 3) * (FK * FROWB);
        const uint32_t vst = sq + FVS_OFF * 4 + (it % 3) * (FK * FROWB);

        // S = Q @ K^T (K fragments via ldmatrix)
        float s[8][4];
#pragma unroll
        for (int j = 0; j < 8; j++)
#pragma unroll
            for (int r = 0; r < 4; r++) s[j][r] = 0.f;
        const uint32_t kbase = kst + lrow * FROWB + lcol;
#pragma unroll
        for (int ks = 0; ks < 4; ks++) {
            unsigned bb[8][2];
#pragma unroll
            for (int jp = 0; jp < 4; jp++) {
                unsigned r[4];
                ldsm4(r, kbase + jp * 16 * FROWB + ks * 32);
                bb[2 * jp][0] = r[0]; bb[2 * jp][1] = r[2];
                bb[2 * jp + 1][0] = r[1]; bb[2 * jp + 1][1] = r[3];
            }
#pragma unroll
            for (int jn = 0; jn < 8; jn++) mma_f16(s[jn], qa[ks], bb[jn]);
        }

        // Online softmax (raw scores; scale*log2e folded, exp2 path)
        float rm0 = -1e30f, rm1 = -1e30f;
#pragma unroll
        for (int j = 0; j < 8; j++) {
            rm0 = fmaxf(rm0, fmaxf(s[j][0], s[j][1]));
            rm1 = fmaxf(rm1, fmaxf(s[j][2], s[j][3]));
        }
        rm0 = fmaxf(rm0, __shfl_xor_sync(0xffffffffu, rm0, 1));
        rm0 = fmaxf(rm0, __shfl_xor_sync(0xffffffffu, rm0, 2));
        rm1 = fmaxf(rm1, __shfl_xor_sync(0xffffffffu, rm1, 1));
        rm1 = fmaxf(rm1, __shfl_xor_sync(0xffffffffu, rm1, 2));
        const float mn0 = fmaxf(m0, rm0), mn1 = fmaxf(m1, rm1);
        const float cr0 = exp2f((m0 - mn0) * SC);
        const float cr1 = exp2f((m1 - mn1) * SC);
        m0 = mn0; m1 = mn1;
        float sum0 = 0.f, sum1 = 0.f;
#pragma unroll
        for (int j = 0; j < 8; j++) {
            s[j][0] = exp2f((s[j][0] - mn0) * SC);
            s[j][1] = exp2f((s[j][1] - mn0) * SC);
            s[j][2] = exp2f((s[j][2] - mn1) * SC);
            s[j][3] = exp2f((s[j][3] - mn1) * SC);
            sum0 += s[j][0] + s[j][1];
            sum1 += s[j][2] + s[j][3];
        }
        sum0 += __shfl_xor_sync(0xffffffffu, sum0, 1);
        sum0 += __shfl_xor_sync(0xffffffffu, sum0, 2);
        sum1 += __shfl_xor_sync(0xffffffffu, sum1, 1);
        sum1 += __shfl_xor_sync(0xffffffffu, sum1, 2);
        l0 = l0 * cr0 + sum0;
        l1 = l1 * cr1 + sum1;
#pragma unroll
        for (int j = 0; j < 8; j++) {
            o[j][0] *= cr0; o[j][1] *= cr0;
            o[j][2] *= cr1; o[j][3] *= cr1;
        }

        // O += P @ V. P repacked in registers as A-fragments; V fragments
        // via ldmatrix.trans on row-major V rows.
        const uint32_t vbase = vst + vrow * FROWB + vcol;
#pragma unroll
        for (int ks = 0; ks < 4; ks++) {
            unsigned pa[4];
            pa[0] = packh2(s[2 * ks][0], s[2 * ks][1]);
            pa[1] = packh2(s[2 * ks][2], s[2 * ks][3]);
            pa[2] = packh2(s[2 * ks + 1][0], s[2 * ks + 1][1]);
            pa[3] = packh2(s[2 * ks + 1][2], s[2 * ks + 1][3]);
            const uint32_t vk = vbase + ks * 16 * FROWB;
#pragma unroll
            for (int jp = 0; jp < 4; jp++) {
                unsigned r[4];
                ldsm4t(r, vk + jp * 32);
                unsigned b0[2] = {r[0], r[1]};
                unsigned b1[2] = {r[2], r[3]};
                mma_f16(o[2 * jp], pa, b0);
                mma_f16(o[2 * jp + 1], pa, b1);
            }
        }
    }

    const float inv0 = 1.f / l0, inv1 = 1.f / l1;
    __half2* out0 = (__half2*)attn + (size_t)(b * SEQ + qb + wq + g) * (HID / 2)
                    + h * (HD / 2);
    __half2* out1 = out0 + (size_t)8 * (HID / 2);
#pragma unroll
    for (int jn = 0; jn < 8; jn++) {
        out0[jn * 4 + t] = __floats2half2_rn(o[jn][0] * inv0, o[jn][1] * inv0);
        out1[jn * 4 + t] = __floats2half2_rn(o[jn][2] * inv1, o[jn][3] * inv1);
    }
}

// ---------------------------------------------------------------------------
extern "C" void kernel_launch(void* const* d_in, const int* in_sizes, int n_in,
                              void* d_out, int out_size) {
    const float* hidden = (const float*)d_in[0];   // [2,2048,1024]
    const float* w_qkv  = (const float*)d_in[1];   // [3072,1024]
    const float* w_o    = (const float*)d_in[2];   // [1024,1024]
    float* out = (float*)d_out;                    // [2,2048,1024]

    __half *hid_h, *wqkv_h, *wo_h, *qkv_h, *attn_h;
    cudaGetSymbolAddress((void**)&hid_h, g_hidden_h);
    cudaGetSymbolAddress((void**)&wqkv_h, g_wqkv_h);
    cudaGetSymbolAddress((void**)&wo_h, g_wo_h);
    cudaGetSymbolAddress((void**)&qkv_h, g_qkv);
    cudaGetSymbolAddress((void**)&attn_h, g_attn);

    static bool attr_set = false;
    if (!attr_set) {
        cudaFuncSetAttribute(gemm_f16<true>,
                             cudaFuncAttributeMaxDynamicSharedMemorySize,
                             GEMM_SMEM);
        cudaFuncSetAttribute(gemm_f16<false>,
                             cudaFuncAttributeMaxDynamicSharedMemorySize,
                             GEMM_SMEM);
        cudaFuncSetAttribute(flash_f16,
                             cudaFuncAttributeMaxDynamicSharedMemorySize,
                             FL_SMEM);
        attr_set = true;
    }

    // 0) fp32 -> fp16 pre-convert (single launch)
    cvt_all<<<(NA + NB + NC) / 1024, 256>>>(hidden, w_qkv, w_o,
                                            hid_h, wqkv_h, wo_h);

    // 1) QKV projection -> g_qkv (half): [4096,1024] @ [3072,1024]^T
    {
        dim3 grid(QKV_COLS / GBN, ROWS / GBM);   // (12, 32)
        gemm_f16<true><<<grid, 512, GEMM_SMEM>>>(hid_h, wqkv_h, qkv_h,
                                                 ROWS, QKV_COLS, HID);
    }

    // 2) Flash attention -> g_attn (half), [B,S,H] layout
    {
        dim3 grid(SEQ / FQ, NH, BATCH);          // (16, 16, 2)
        flash_f16<<<grid, 256, FL_SMEM>>>(qkv_h, attn_h);
    }

    // 3) Output projection -> fp32 out: [4096,1024] @ [1024,1024]^T
    {
        dim3 grid(HID / GBN, ROWS / GBM);        // (4, 32)
        gemm_f16<false><<<grid, 512, GEMM_SMEM>>>(attn_h, wo_h, out,
                                                  ROWS, HID, HID);
    }
}